// round 6
// baseline (speedup 1.0000x reference)
#include <cuda_runtime.h>
#include <cuda_bf16.h>
#include <math.h>
#include <stdint.h>

// Problem shape: B=4, T=2048, D=512, H=8, Hd=64, FFN=2048
#define T_SEQ   2048
#define DIM     512
#define NHEAD   8
#define HDIM    64
#define FFN_DIM 2048
#define MAX_BT  8192

// ======================= helpers =======================
__device__ __forceinline__ uint32_t smem_u32(const void* p) {
    uint32_t a;
    asm("{ .reg .u64 t; cvta.to.shared.u64 t, %1; cvt.u32.u64 %0, t; }" : "=r"(a) : "l"(p));
    return a;
}
__device__ __forceinline__ void cp16(uint32_t s, const void* g) {
    asm volatile("cp.async.ca.shared.global [%0], [%1], 16;" :: "r"(s), "l"(g));
}
#define CP_COMMIT() asm volatile("cp.async.commit_group;" ::: "memory")
#define CP_WAIT2()  asm volatile("cp.async.wait_group 2;" ::: "memory")

__device__ __forceinline__ void ldsm4(uint32_t* r, uint32_t addr) {
    asm volatile("ldmatrix.sync.aligned.m8n8.x4.shared.b16 {%0,%1,%2,%3}, [%4];"
        : "=r"(r[0]), "=r"(r[1]), "=r"(r[2]), "=r"(r[3]) : "r"(addr));
}
__device__ __forceinline__ void imma(int32_t* c, const uint32_t* a, const uint32_t* b) {
    asm volatile(
        "mma.sync.aligned.m16n8k32.row.col.s32.s8.s8.s32 "
        "{%0,%1,%2,%3}, {%4,%5,%6,%7}, {%8,%9}, {%0,%1,%2,%3};"
        : "+r"(c[0]), "+r"(c[1]), "+r"(c[2]), "+r"(c[3])
        : "r"(a[0]), "r"(a[1]), "r"(a[2]), "r"(a[3]), "r"(b[0]), "r"(b[1]));
}
// quantize x in [-1,1] (pre-divided by scale) -> q1 + q2/254, both in [-127,127]
__device__ __forceinline__ void quant2(float x, int8_t& q1, int8_t& q2) {
    float a1 = rintf(x * 127.0f);
    a1 = fminf(fmaxf(a1, -127.0f), 127.0f);
    float r = fmaf(x, 127.0f, -a1);
    float a2 = rintf(r * 254.0f);
    a2 = fminf(fmaxf(a2, -127.0f), 127.0f);
    q1 = (int8_t)(int)a1;
    q2 = (int8_t)(int)a2;
}

// ======================= scratch =======================
__device__ int8_t g_wqkv1[3 * DIM * DIM], g_wqkv2[3 * DIM * DIM];
__device__ int8_t g_wout1[DIM * DIM],     g_wout2[DIM * DIM];
__device__ int8_t g_w11[FFN_DIM * DIM],   g_w12[FFN_DIM * DIM];
__device__ int8_t g_w21[DIM * FFN_DIM],   g_w22[DIM * FFN_DIM];
__device__ float  g_swqkv[3 * DIM], g_swout[DIM], g_sw1[FFN_DIM], g_sw2[DIM];
__device__ int8_t g_xq1[MAX_BT * DIM],  g_xq2[MAX_BT * DIM];
__device__ int8_t g_cq1[MAX_BT * DIM],  g_cq2[MAX_BT * DIM];
__device__ int8_t g_hq1[MAX_BT * FFN_DIM], g_hq2[MAX_BT * FFN_DIM];
__device__ float  g_sx[MAX_BT], g_sc[MAX_BT], g_sh[MAX_BT];
__device__ float  g_qkv[MAX_BT * 3 * DIM];
__device__ float  g_ctxf[MAX_BT * DIM];
__device__ float  g_x1[MAX_BT * DIM];
__device__ float  g_hf[MAX_BT * FFN_DIM];

// ============ weight prep: W[K][N] fp32 -> T1,T2 int8 [N][K] + per-col scale ============
__global__ void wprep_i8(const float* __restrict__ W,
                         int8_t* __restrict__ T1, int8_t* __restrict__ T2,
                         float* __restrict__ sB, int K, int N) {
    __shared__ float smax[8][32];
    __shared__ float t[32][33];
    __shared__ float scol[32];
    const int n0 = blockIdx.x * 32;
    const int tx = threadIdx.x, ty = threadIdx.y;
    const int col = n0 + tx;
    // pass 1: column max
    float m = 0.0f;
    for (int k = ty; k < K; k += 8)
        m = fmaxf(m, fabsf(W[(size_t)k * N + col]));
    smax[ty][tx] = m;
    __syncthreads();
    if (ty == 0) {
        float s = smax[0][tx];
        #pragma unroll
        for (int i = 1; i < 8; ++i) s = fmaxf(s, smax[i][tx]);
        s = (s > 0.0f) ? s : 1.0f;
        scol[tx] = s;
        sB[col] = s;
    }
    __syncthreads();
    // pass 2: transpose + quantize
    for (int k0 = 0; k0 < K; k0 += 32) {
        #pragma unroll
        for (int i = 0; i < 4; ++i)
            t[ty + i * 8][tx] = W[(size_t)(k0 + ty + i * 8) * N + col];
        __syncthreads();
        #pragma unroll
        for (int i = 0; i < 4; ++i) {
            const int nl = ty + i * 8;
            const float x = t[tx][nl] / scol[nl];
            int8_t q1, q2;
            quant2(x, q1, q2);
            const size_t o = (size_t)(n0 + nl) * K + k0 + tx;
            T1[o] = q1;
            T2[o] = q2;
        }
        __syncthreads();
    }
}

// ============ rmsnorm -> int8 q1/q2 + per-row scale ============
__global__ void rmsnorm_q_kernel(const float* __restrict__ x,
                                 const float* __restrict__ w,
                                 int8_t* __restrict__ Q1, int8_t* __restrict__ Q2,
                                 float* __restrict__ S) {
    const int row = blockIdx.x;
    const int tid = threadIdx.x;  // 128
    const float4 v = reinterpret_cast<const float4*>(x + (size_t)row * DIM)[tid];
    float ss = v.x * v.x + v.y * v.y + v.z * v.z + v.w * v.w;
    #pragma unroll
    for (int off = 16; off > 0; off >>= 1)
        ss += __shfl_xor_sync(0xFFFFFFFFu, ss, off);
    __shared__ float red[4];
    __shared__ float redm[4];
    __shared__ float ssh;
    const int warp = tid >> 5, lane = tid & 31;
    if (lane == 0) red[warp] = ss;
    __syncthreads();
    const float r = rsqrtf((red[0] + red[1] + red[2] + red[3]) * (1.0f / DIM) + 1e-6f);
    const float4 wv = reinterpret_cast<const float4*>(w)[tid];
    float y[4] = {v.x * r * wv.x, v.y * r * wv.y, v.z * r * wv.z, v.w * r * wv.w};
    float m = fmaxf(fmaxf(fabsf(y[0]), fabsf(y[1])), fmaxf(fabsf(y[2]), fabsf(y[3])));
    #pragma unroll
    for (int off = 16; off > 0; off >>= 1)
        m = fmaxf(m, __shfl_xor_sync(0xFFFFFFFFu, m, off));
    if (lane == 0) redm[warp] = m;
    __syncthreads();
    if (tid == 0) {
        float s = fmaxf(fmaxf(redm[0], redm[1]), fmaxf(redm[2], redm[3]));
        s = (s > 0.0f) ? s : 1.0f;
        ssh = s;
        S[row] = s;
    }
    __syncthreads();
    const float inv = 1.0f / ssh;
    uchar4 p1, p2;
    int8_t q1[4], q2[4];
    #pragma unroll
    for (int j = 0; j < 4; ++j) quant2(y[j] * inv, q1[j], q2[j]);
    p1 = {(unsigned char)q1[0], (unsigned char)q1[1], (unsigned char)q1[2], (unsigned char)q1[3]};
    p2 = {(unsigned char)q2[0], (unsigned char)q2[1], (unsigned char)q2[2], (unsigned char)q2[3]};
    *reinterpret_cast<uchar4*>(Q1 + (size_t)row * DIM + tid * 4) = p1;
    *reinterpret_cast<uchar4*>(Q2 + (size_t)row * DIM + tid * 4) = p2;
}

// ============ generic row quantizer: X[M][N] fp32 -> int8 + row scale ============
__global__ void quant_rows_kernel(const float* __restrict__ X,
                                  int8_t* __restrict__ Q1, int8_t* __restrict__ Q2,
                                  float* __restrict__ S, int N) {
    const int row = blockIdx.x;
    const int tid = threadIdx.x;  // 128
    const int nch = N / 512;      // 1 or 4 chunks of float4
    float v[16];
    float m = 0.0f;
    for (int c = 0; c < nch; ++c) {
        const float4 f = reinterpret_cast<const float4*>(X + (size_t)row * N)[c * 128 + tid];
        v[c * 4 + 0] = f.x; v[c * 4 + 1] = f.y; v[c * 4 + 2] = f.z; v[c * 4 + 3] = f.w;
        m = fmaxf(m, fmaxf(fmaxf(fabsf(f.x), fabsf(f.y)), fmaxf(fabsf(f.z), fabsf(f.w))));
    }
    #pragma unroll
    for (int off = 16; off > 0; off >>= 1)
        m = fmaxf(m, __shfl_xor_sync(0xFFFFFFFFu, m, off));
    __shared__ float redm[4];
    __shared__ float ssh;
    const int warp = tid >> 5, lane = tid & 31;
    if (lane == 0) redm[warp] = m;
    __syncthreads();
    if (tid == 0) {
        float s = fmaxf(fmaxf(redm[0], redm[1]), fmaxf(redm[2], redm[3]));
        s = (s > 0.0f) ? s : 1.0f;
        ssh = s;
        S[row] = s;
    }
    __syncthreads();
    const float inv = 1.0f / ssh;
    for (int c = 0; c < nch; ++c) {
        int8_t q1[4], q2[4];
        #pragma unroll
        for (int j = 0; j < 4; ++j) quant2(v[c * 4 + j] * inv, q1[j], q2[j]);
        uchar4 p1 = {(unsigned char)q1[0], (unsigned char)q1[1], (unsigned char)q1[2], (unsigned char)q1[3]};
        uchar4 p2 = {(unsigned char)q2[0], (unsigned char)q2[1], (unsigned char)q2[2], (unsigned char)q2[3]};
        *reinterpret_cast<uchar4*>(Q1 + (size_t)row * N + (c * 128 + tid) * 4) = p1;
        *reinterpret_cast<uchar4*>(Q2 + (size_t)row * N + (c * 128 + tid) * 4) = p2;
    }
}

// ======================= int8 IMMA GEMM =======================
// C[M,N] = sA[m]*sB[n]*( acc_hi/127^2 + acc_mid/(127^2*254) )
// A1,A2[M][K], B1,B2[N][K] int8 row-major (K-major). 128x128 tile, 8 warps (64x32),
// K-slab 64 int8 (= 32 "b16 units"), 4-stage cp.async, 1 sync/slab.
// SMEM row: 64B data + 16B pad = 80B. EPI: 0 plain, 1 +bias+resid, 2 +bias+gelu.
#define PADK   40                     // b16 units per row (80 B)
#define MATB   (128 * 80)             // 10240 B per matrix part
#define STAGEB (4 * MATB)             // A1,A2,B1,B2 = 40960 B
#define NSTAGE 4
#define GEMM_DSMEM (NSTAGE * STAGEB)  // 163840 B

template <int EPI>
__global__ __launch_bounds__(256, 1)
void gemm_i8(const int8_t* __restrict__ A1, const int8_t* __restrict__ A2,
             const float* __restrict__ sA,
             const int8_t* __restrict__ B1, const int8_t* __restrict__ B2,
             const float* __restrict__ sB,
             const float* __restrict__ bias, const float* __restrict__ R,
             float* __restrict__ C, int M, int N, int K) {
    extern __shared__ char dsm[];
    const uint32_t sm0 = smem_u32(dsm);
    const int tid = threadIdx.x;
    const int wid = tid >> 5;
    const int lane = tid & 31;
    const int wm = wid & 1;
    const int wn = wid >> 1;
    const int bm = blockIdx.y * 128;
    const int bn = blockIdx.x * 128;
    const int NS = K / 64;

    auto load_slab = [&](int s) {
        const uint32_t st = sm0 + (uint32_t)(s & (NSTAGE - 1)) * STAGEB;
        const int k0 = s * 64;
        #pragma unroll
        for (int i = 0; i < 2; ++i) {
            const int idx = tid + i * 256;       // 0..511
            const int row = idx >> 2;            // 0..127
            const int c   = idx & 3;             // 0..3
            const uint32_t so = (uint32_t)(row * 80 + c * 16);
            const size_t gA = (size_t)(bm + row) * K + k0 + c * 16;
            const size_t gB = (size_t)(bn + row) * K + k0 + c * 16;
            cp16(st + 0 * MATB + so, A1 + gA);
            cp16(st + 1 * MATB + so, A2 + gA);
            cp16(st + 2 * MATB + so, B1 + gB);
            cp16(st + 3 * MATB + so, B2 + gB);
        }
    };

    int32_t hi[4][4][4] = {};
    int32_t mid[4][4][4] = {};

    load_slab(0); CP_COMMIT();
    load_slab(1); CP_COMMIT();
    load_slab(2); CP_COMMIT();

    // ldmatrix offsets in "b16 units" (1 unit = 2 int8)
    const uint32_t aRow = (uint32_t)(wm * 64 + (lane & 15));
    const uint32_t aKo  = (uint32_t)((lane >> 4) * 8);
    const uint32_t bRow = (uint32_t)(wn * 32 + (lane & 7) + ((lane >> 4) << 3));
    const uint32_t bKo  = (uint32_t)(((lane >> 3) & 1) * 8);

    for (int s = 0; s < NS; ++s) {
        CP_WAIT2();
        __syncthreads();
        if (s + 3 < NS) load_slab(s + 3);
        CP_COMMIT();
        const uint32_t st = sm0 + (uint32_t)(s & (NSTAGE - 1)) * STAGEB;

        #pragma unroll
        for (int kk = 0; kk < 32; kk += 16) {   // two k32 chunks (16 b16 units each)
            uint32_t a1f[4][4], a2f[4][4], b1f[2][4], b2f[2][4];
            #pragma unroll
            for (int mi = 0; mi < 4; ++mi) {
                const uint32_t off = ((aRow + mi * 16) * PADK + kk + aKo) * 2;
                ldsm4(a1f[mi], st + 0 * MATB + off);
                ldsm4(a2f[mi], st + 1 * MATB + off);
            }
            #pragma unroll
            for (int g = 0; g < 2; ++g) {
                const uint32_t off = ((bRow + g * 16) * PADK + kk + bKo) * 2;
                ldsm4(b1f[g], st + 2 * MATB + off);
                ldsm4(b2f[g], st + 3 * MATB + off);
            }
            #pragma unroll
            for (int mi = 0; mi < 4; ++mi) {
                #pragma unroll
                for (int ni = 0; ni < 4; ++ni) {
                    const int g = ni >> 1, sub = (ni & 1) * 2;
                    imma(hi[mi][ni],  a1f[mi], &b1f[g][sub]);
                    imma(mid[mi][ni], a1f[mi], &b2f[g][sub]);
                    imma(mid[mi][ni], a2f[mi], &b1f[g][sub]);
                }
            }
        }
    }

    // epilogue
    const float C1 = 1.0f / (127.0f * 127.0f);
    const float C2 = C1 / 254.0f;
    const int cbase = bn + wn * 32 + (lane & 3) * 2;
    const int rbase = bm + wm * 64 + (lane >> 2);
    float sbv[4][2];
    #pragma unroll
    for (int ni = 0; ni < 4; ++ni) {
        sbv[ni][0] = sB[cbase + ni * 8];
        sbv[ni][1] = sB[cbase + ni * 8 + 1];
    }
    #pragma unroll
    for (int mi = 0; mi < 4; ++mi) {
        #pragma unroll
        for (int half = 0; half < 2; ++half) {
            const int row = rbase + mi * 16 + half * 8;
            const float sa = sA[row];
            #pragma unroll
            for (int ni = 0; ni < 4; ++ni) {
                const int col = cbase + ni * 8;
                float v0 = sa * sbv[ni][0] *
                    ((float)hi[mi][ni][half * 2 + 0] * C1 + (float)mid[mi][ni][half * 2 + 0] * C2);
                float v1 = sa * sbv[ni][1] *
                    ((float)hi[mi][ni][half * 2 + 1] * C1 + (float)mid[mi][ni][half * 2 + 1] * C2);
                if (EPI == 0) {
                    *(float2*)(C + (size_t)row * N + col) = {v0, v1};
                } else if (EPI == 1) {
                    const float2 rv = *(const float2*)(R + (size_t)row * N + col);
                    v0 += bias[col]     + rv.x;
                    v1 += bias[col + 1] + rv.y;
                    *(float2*)(C + (size_t)row * N + col) = {v0, v1};
                } else {
                    const float t0 = v0 + bias[col];
                    const float t1 = v1 + bias[col + 1];
                    const float g0 = 0.5f * t0 * (1.0f + erff(t0 * 0.70710678118654752f));
                    const float g1 = 0.5f * t1 * (1.0f + erff(t1 * 0.70710678118654752f));
                    *(float2*)(C + (size_t)row * N + col) = {g0, g1};
                }
            }
        }
    }
}

// ======================= banded attention (q-tiled, SMEM K/V) -> fp32 ctx =======================
#define ATT_KBYTES (192 * 64 * 4)
#define ATT_DSMEM  (2 * ATT_KBYTES + 8 * 136 * 4)

__global__ __launch_bounds__(256, 1)
void attn_kernel(const float* __restrict__ qkv,
                 float* __restrict__ ctxf,
                 const int* __restrict__ csp, int T) {
    extern __shared__ char dsm[];
    float* Ks = (float*)dsm;
    float* Vs = (float*)(dsm + ATT_KBYTES);
    float* scb = (float*)(dsm + 2 * ATT_KBYTES);

    const int cs = min(*csp, 64);
    const int tid = threadIdx.x;
    const int wid = tid >> 5;
    const int lane = tid & 31;
    const int q0 = blockIdx.x * 64;
    const int h = blockIdx.y;
    const int b = blockIdx.z;

    const int jlo = max(q0 - cs, 0);
    const int jhi = min(q0 + 63 + cs, T - 1);
    const int nk = jhi - jlo + 1;

    for (int i = tid; i < nk * 16; i += 256) {
        const int row = i >> 4, c = i & 15;
        const float4* src = (const float4*)(qkv + (size_t)(b * T + jlo + row) * (3 * DIM) + h * HDIM);
        ((float4*)Ks)[row * 16 + c] = src[c + 128];
        ((float4*)Vs)[row * 16 + c] = src[c + 256];
    }
    __syncthreads();

    float* sc = scb + wid * 136;
    const float scale = 0.125f;

    for (int qi = 0; qi < 8; ++qi) {
        const int t = q0 + wid * 8 + qi;
        const float2 qv = *(const float2*)(qkv + (size_t)(b * T + t) * (3 * DIM) + h * HDIM + 2 * lane);
        const int jloq = max(t - cs, 0);
        const int jhiq = min(t + cs, T - 1);
        const int base = jloq - jlo;
        const int n = jhiq - jloq + 1;

        float mx = -INFINITY;
        for (int j = 0; j < n; ++j) {
            const float2 kk = *(const float2*)(Ks + (base + j) * 64 + 2 * lane);
            float s = qv.x * kk.x + qv.y * kk.y;
            #pragma unroll
            for (int off = 16; off > 0; off >>= 1)
                s += __shfl_xor_sync(0xFFFFFFFFu, s, off);
            s *= scale;
            mx = fmaxf(mx, s);
            if (lane == 0) sc[j] = s;
        }
        __syncwarp();

        float sum = 0.0f;
        for (int i = lane; i < n; i += 32) {
            const float p = __expf(sc[i] - mx);
            sc[i] = p;
            sum += p;
        }
        #pragma unroll
        for (int off = 16; off > 0; off >>= 1)
            sum += __shfl_xor_sync(0xFFFFFFFFu, sum, off);
        const float inv = 1.0f / sum;
        __syncwarp();

        float2 acc = {0.0f, 0.0f};
        for (int j = 0; j < n; ++j) {
            const float p = sc[j];
            const float2 vv = *(const float2*)(Vs + (base + j) * 64 + 2 * lane);
            acc.x = fmaf(p, vv.x, acc.x);
            acc.y = fmaf(p, vv.y, acc.y);
        }
        *(float2*)(ctxf + (size_t)(b * T + t) * DIM + h * HDIM + 2 * lane) = {acc.x * inv, acc.y * inv};
        __syncwarp();
    }
}

// ======================= launcher =======================
extern "C" void kernel_launch(void* const* d_in, const int* in_sizes, int n_in,
                              void* d_out, int out_size) {
    const float* x       = (const float*)d_in[0];
    const float* norm1_w = (const float*)d_in[1];
    const float* norm2_w = (const float*)d_in[2];
    const float* w_qkv   = (const float*)d_in[3];
    const float* w_out   = (const float*)d_in[4];
    const float* b_out   = (const float*)d_in[5];
    const float* w1      = (const float*)d_in[6];
    const float* b1      = (const float*)d_in[7];
    const float* w2      = (const float*)d_in[8];
    const float* b2      = (const float*)d_in[9];
    const int*   cs      = (const int*)d_in[10];
    float*       out     = (float*)d_out;

    const int BT = in_sizes[0] / DIM;   // 8192
    const int T  = T_SEQ;
    const int B  = BT / T;

    int8_t *wqkv1, *wqkv2, *wout1, *wout2, *w11, *w12, *w21, *w22;
    int8_t *xq1, *xq2, *cq1, *cq2, *hq1, *hq2;
    float *swqkv, *swout, *sw1, *sw2, *sx, *sctx, *sh;
    float *qkv, *ctxf, *x1, *hf;
    cudaGetSymbolAddress((void**)&wqkv1, g_wqkv1);
    cudaGetSymbolAddress((void**)&wqkv2, g_wqkv2);
    cudaGetSymbolAddress((void**)&wout1, g_wout1);
    cudaGetSymbolAddress((void**)&wout2, g_wout2);
    cudaGetSymbolAddress((void**)&w11,   g_w11);
    cudaGetSymbolAddress((void**)&w12,   g_w12);
    cudaGetSymbolAddress((void**)&w21,   g_w21);
    cudaGetSymbolAddress((void**)&w22,   g_w22);
    cudaGetSymbolAddress((void**)&swqkv, g_swqkv);
    cudaGetSymbolAddress((void**)&swout, g_swout);
    cudaGetSymbolAddress((void**)&sw1,   g_sw1);
    cudaGetSymbolAddress((void**)&sw2,   g_sw2);
    cudaGetSymbolAddress((void**)&xq1,   g_xq1);
    cudaGetSymbolAddress((void**)&xq2,   g_xq2);
    cudaGetSymbolAddress((void**)&cq1,   g_cq1);
    cudaGetSymbolAddress((void**)&cq2,   g_cq2);
    cudaGetSymbolAddress((void**)&hq1,   g_hq1);
    cudaGetSymbolAddress((void**)&hq2,   g_hq2);
    cudaGetSymbolAddress((void**)&sx,    g_sx);
    cudaGetSymbolAddress((void**)&sctx,  g_sc);
    cudaGetSymbolAddress((void**)&sh,    g_sh);
    cudaGetSymbolAddress((void**)&qkv,   g_qkv);
    cudaGetSymbolAddress((void**)&ctxf,  g_ctxf);
    cudaGetSymbolAddress((void**)&x1,    g_x1);
    cudaGetSymbolAddress((void**)&hf,    g_hf);

    cudaFuncSetAttribute(gemm_i8<0>, cudaFuncAttributeMaxDynamicSharedMemorySize, GEMM_DSMEM);
    cudaFuncSetAttribute(gemm_i8<1>, cudaFuncAttributeMaxDynamicSharedMemorySize, GEMM_DSMEM);
    cudaFuncSetAttribute(gemm_i8<2>, cudaFuncAttributeMaxDynamicSharedMemorySize, GEMM_DSMEM);
    cudaFuncSetAttribute(attn_kernel, cudaFuncAttributeMaxDynamicSharedMemorySize, ATT_DSMEM);

    const dim3 wb(32, 8);
    wprep_i8<<<(3 * DIM) / 32, wb>>>(w_qkv, wqkv1, wqkv2, swqkv, DIM, 3 * DIM);
    wprep_i8<<<DIM / 32,       wb>>>(w_out, wout1, wout2, swout, DIM, DIM);
    wprep_i8<<<FFN_DIM / 32,   wb>>>(w1,    w11,   w12,   sw1,   DIM, FFN_DIM);
    wprep_i8<<<DIM / 32,       wb>>>(w2,    w21,   w22,   sw2,   FFN_DIM, DIM);

    // 1. xn = rmsnorm(x, norm1_w) -> int8
    rmsnorm_q_kernel<<<BT, 128>>>(x, norm1_w, xq1, xq2, sx);
    // 2. qkv = xn @ w_qkv (fp32)
    gemm_i8<0><<<dim3((3 * DIM) / 128, BT / 128), 256, GEMM_DSMEM>>>(
        xq1, xq2, sx, wqkv1, wqkv2, swqkv, nullptr, nullptr, qkv, BT, 3 * DIM, DIM);
    // 3. attention -> ctx fp32
    attn_kernel<<<dim3(T / 64, NHEAD, B), 256, ATT_DSMEM>>>(qkv, ctxf, cs, T);
    // 3b. quantize ctx rows
    quant_rows_kernel<<<BT, 128>>>(ctxf, cq1, cq2, sctx, DIM);
    // 4. x1 = x + ctx @ w_out + b_out
    gemm_i8<1><<<dim3(DIM / 128, BT / 128), 256, GEMM_DSMEM>>>(
        cq1, cq2, sctx, wout1, wout2, swout, b_out, x, x1, BT, DIM, DIM);
    // 5. xn = rmsnorm(x1, norm2_w) -> int8
    rmsnorm_q_kernel<<<BT, 128>>>(x1, norm2_w, xq1, xq2, sx);
    // 6. h = gelu(xn @ w1 + b1) -> fp32
    gemm_i8<2><<<dim3(FFN_DIM / 128, BT / 128), 256, GEMM_DSMEM>>>(
        xq1, xq2, sx, w11, w12, sw1, b1, nullptr, hf, BT, FFN_DIM, DIM);
    // 6b. quantize h rows
    quant_rows_kernel<<<BT, 128>>>(hf, hq1, hq2, sh, FFN_DIM);
    // 7. out = x1 + h @ w2 + b2
    gemm_i8<1><<<dim3(DIM / 128, BT / 128), 256, GEMM_DSMEM>>>(
        hq1, hq2, sh, w21, w22, sw2, b2, x1, out, BT, DIM, FFN_DIM);
}

// round 7
// speedup vs baseline: 1.8408x; 1.8408x over previous
#include <cuda_runtime.h>
#include <cuda_bf16.h>
#include <math.h>
#include <stdint.h>

// Problem shape (fixed by the dataset): B=4, T=2048, D=512, H=8, Hd=64, FFN=2048
#define T_SEQ   2048
#define DIM     512
#define NHEAD   8
#define HDIM    64
#define FFN_DIM 2048
#define MAX_BT  8192

// ======================= helpers =======================
__device__ __forceinline__ uint32_t smem_u32(const void* p) {
    uint32_t a;
    asm("{ .reg .u64 t; cvta.to.shared.u64 t, %1; cvt.u32.u64 %0, t; }" : "=r"(a) : "l"(p));
    return a;
}
__device__ __forceinline__ void cp16(uint32_t s, const void* g) {
    asm volatile("cp.async.ca.shared.global [%0], [%1], 16;" :: "r"(s), "l"(g));
}
#define CP_COMMIT() asm volatile("cp.async.commit_group;" ::: "memory")
#define CP_WAIT1()  asm volatile("cp.async.wait_group 1;" ::: "memory")

__device__ __forceinline__ void ldsm4(uint32_t* r, uint32_t addr) {
    asm volatile("ldmatrix.sync.aligned.m8n8.x4.shared.b16 {%0,%1,%2,%3}, [%4];"
        : "=r"(r[0]), "=r"(r[1]), "=r"(r[2]), "=r"(r[3]) : "r"(addr));
}
__device__ __forceinline__ void mma_bf16(float* c, const uint32_t* a, const uint32_t* b) {
    asm volatile(
        "mma.sync.aligned.m16n8k16.row.col.f32.bf16.bf16.f32 "
        "{%0,%1,%2,%3}, {%4,%5,%6,%7}, {%8,%9}, {%0,%1,%2,%3};"
        : "+f"(c[0]), "+f"(c[1]), "+f"(c[2]), "+f"(c[3])
        : "r"(a[0]), "r"(a[1]), "r"(a[2]), "r"(a[3]), "r"(b[0]), "r"(b[1]));
}
__device__ __forceinline__ void split2(float f, __nv_bfloat16& h, __nv_bfloat16& l) {
    h = __float2bfloat16(f);
    l = __float2bfloat16(f - __bfloat162float(h));
}

// ======================= scratch =======================
__device__ __nv_bfloat16 g_wqkvT_h[3 * DIM * DIM], g_wqkvT_l[3 * DIM * DIM];
__device__ __nv_bfloat16 g_woutT_h[DIM * DIM],     g_woutT_l[DIM * DIM];
__device__ __nv_bfloat16 g_w1T_h[FFN_DIM * DIM],   g_w1T_l[FFN_DIM * DIM];
__device__ __nv_bfloat16 g_w2T_h[DIM * FFN_DIM],   g_w2T_l[DIM * FFN_DIM];
__device__ __nv_bfloat16 g_xn_h[MAX_BT * DIM],     g_xn_l[MAX_BT * DIM];
__device__ __nv_bfloat16 g_ctx_h[MAX_BT * DIM],    g_ctx_l[MAX_BT * DIM];
__device__ __nv_bfloat16 g_hh[MAX_BT * FFN_DIM],   g_hl[MAX_BT * FFN_DIM];
__device__ float g_qkv[MAX_BT * 3 * DIM];
__device__ float g_x1[MAX_BT * DIM];

// ======================= weight prep: W[K][N] -> WT hi/lo [N][K] =======================
__global__ void wprep_kernel(const float* __restrict__ W,
                             __nv_bfloat16* __restrict__ Th,
                             __nv_bfloat16* __restrict__ Tl,
                             int K, int N) {
    __shared__ float t[32][33];
    const int n0 = blockIdx.x * 32, k0 = blockIdx.y * 32;
    const int tx = threadIdx.x, ty = threadIdx.y;
    #pragma unroll
    for (int i = 0; i < 4; ++i)
        t[ty + i * 8][tx] = W[(size_t)(k0 + ty + i * 8) * N + n0 + tx];
    __syncthreads();
    #pragma unroll
    for (int i = 0; i < 4; ++i) {
        const float v = t[tx][ty + i * 8];
        __nv_bfloat16 h, l;
        split2(v, h, l);
        const size_t o = (size_t)(n0 + ty + i * 8) * K + k0 + tx;
        Th[o] = h;
        Tl[o] = l;
    }
}

// ======================= rmsnorm -> bf16 hi/lo =======================
__global__ void rmsnorm_split_kernel(const float* __restrict__ x,
                                     const float* __restrict__ w,
                                     __nv_bfloat16* __restrict__ yh,
                                     __nv_bfloat16* __restrict__ yl) {
    const int row = blockIdx.x;
    const int tid = threadIdx.x;  // 128
    const float4 v = reinterpret_cast<const float4*>(x + (size_t)row * DIM)[tid];
    float ss = v.x * v.x + v.y * v.y + v.z * v.z + v.w * v.w;
    #pragma unroll
    for (int off = 16; off > 0; off >>= 1)
        ss += __shfl_xor_sync(0xFFFFFFFFu, ss, off);
    __shared__ float red[4];
    const int warp = tid >> 5, lane = tid & 31;
    if (lane == 0) red[warp] = ss;
    __syncthreads();
    const float r = rsqrtf((red[0] + red[1] + red[2] + red[3]) * (1.0f / DIM) + 1e-6f);
    const float4 wv = reinterpret_cast<const float4*>(w)[tid];
    float o[4] = {v.x * r * wv.x, v.y * r * wv.y, v.z * r * wv.z, v.w * r * wv.w};
    __nv_bfloat16 h[4], l[4];
    #pragma unroll
    for (int j = 0; j < 4; ++j) split2(o[j], h[j], l[j]);
    const size_t e = (size_t)row * DIM + tid * 4;
    *reinterpret_cast<__nv_bfloat162*>(yh + e)     = {h[0], h[1]};
    *reinterpret_cast<__nv_bfloat162*>(yh + e + 2) = {h[2], h[3]};
    *reinterpret_cast<__nv_bfloat162*>(yl + e)     = {l[0], l[1]};
    *reinterpret_cast<__nv_bfloat162*>(yl + e + 2) = {l[2], l[3]};
}

// ======================= mma.sync GEMM =======================
// C[M,N] = sum_k A[M,K]*B^T[N,K]; A,B pre-split bf16 hi/lo, K-major rows.
// 128x128 block tile, 8 warps (64x32 each), K-slab 32, cp.async double buffer.
// __launch_bounds__(256,2): 2 CTAs/SM (smem 2x80KB=160KB <= 227KB, regs <=128).
// A-fragments loaded inside the mi loop to keep register pressure under 128.
// EPI: 0 = fp32 C; 1 = +bias +resid -> fp32 C; 2 = +bias, gelu -> bf16 hi/lo
#define PADK   40
#define MATB   (128 * PADK * 2)      // 10240 bytes per matrix tile
#define STAGEB (4 * MATB)            // Ah, Al, Bh, Bl
#define GEMM_DSMEM (2 * STAGEB)      // 81920

template <int EPI>
__global__ __launch_bounds__(256, 2)
void gemm_mma(const __nv_bfloat16* __restrict__ Ahi, const __nv_bfloat16* __restrict__ Alo,
              const __nv_bfloat16* __restrict__ Bhi, const __nv_bfloat16* __restrict__ Blo,
              const float* __restrict__ bias, const float* __restrict__ R,
              float* __restrict__ C,
              __nv_bfloat16* __restrict__ Chi, __nv_bfloat16* __restrict__ Clo,
              int M, int N, int K) {
    extern __shared__ char dsm[];
    const uint32_t sm0 = smem_u32(dsm);
    const int tid = threadIdx.x;
    const int wid = tid >> 5;
    const int lane = tid & 31;
    const int wm = wid & 1;             // 0..1 over M
    const int wn = wid >> 1;            // 0..3 over N
    const int bm = blockIdx.y * 128;
    const int bn = blockIdx.x * 128;

    const int NS = K / 32;

    auto load_slab = [&](int s) {
        const uint32_t st = sm0 + (uint32_t)(s & 1) * STAGEB;
        const int k0 = s * 32;
        #pragma unroll
        for (int i = 0; i < 2; ++i) {
            const int idx = tid + i * 256;        // 0..511
            const int row = idx >> 2;             // 0..127
            const int c   = idx & 3;              // 0..3
            const uint32_t so = (uint32_t)(row * 80 + c * 16);
            const size_t gA = (size_t)(bm + row) * K + k0 + c * 8;
            const size_t gB = (size_t)(bn + row) * K + k0 + c * 8;
            cp16(st + 0 * MATB + so, Ahi + gA);
            cp16(st + 1 * MATB + so, Alo + gA);
            cp16(st + 2 * MATB + so, Bhi + gB);
            cp16(st + 3 * MATB + so, Blo + gB);
        }
    };

    float acc[4][4][4] = {};

    load_slab(0); CP_COMMIT();
    if (NS > 1) { load_slab(1); }
    CP_COMMIT();

    // ldmatrix base offsets (within-tile), fixed per thread
    const uint32_t aRow = (uint32_t)(wm * 64 + (lane & 15));
    const uint32_t aKo  = (uint32_t)((lane >> 4) * 8);
    const uint32_t bRow = (uint32_t)(wn * 32 + (lane & 7) + ((lane >> 4) << 3));
    const uint32_t bKo  = (uint32_t)(((lane >> 3) & 1) * 8);

    for (int s = 0; s < NS; ++s) {
        CP_WAIT1();
        __syncthreads();
        const uint32_t st = sm0 + (uint32_t)(s & 1) * STAGEB;

        #pragma unroll
        for (int kk = 0; kk < 32; kk += 16) {
            uint32_t bh[2][4], bl[2][4];
            #pragma unroll
            for (int g = 0; g < 2; ++g) {
                const uint32_t off = ((bRow + g * 16) * PADK + kk + bKo) * 2;
                ldsm4(bh[g], st + 2 * MATB + off);
                ldsm4(bl[g], st + 3 * MATB + off);
            }
            #pragma unroll
            for (int mi = 0; mi < 4; ++mi) {
                uint32_t ah[4], al[4];
                const uint32_t off = ((aRow + mi * 16) * PADK + kk + aKo) * 2;
                ldsm4(ah, st + 0 * MATB + off);
                ldsm4(al, st + 1 * MATB + off);
                #pragma unroll
                for (int ni = 0; ni < 4; ++ni) {
                    const int g = ni >> 1, sub = (ni & 1) * 2;
                    mma_bf16(acc[mi][ni], ah, &bh[g][sub]);
                    mma_bf16(acc[mi][ni], ah, &bl[g][sub]);
                    mma_bf16(acc[mi][ni], al, &bh[g][sub]);
                }
            }
        }
        __syncthreads();
        if (s + 2 < NS) load_slab(s + 2);
        CP_COMMIT();
    }

    // epilogue: acc -> gmem (thread holds pairs of consecutive cols)
    const int cbase = bn + wn * 32 + (lane & 3) * 2;
    const int rbase = bm + wm * 64 + (lane >> 2);
    #pragma unroll
    for (int mi = 0; mi < 4; ++mi) {
        #pragma unroll
        for (int ni = 0; ni < 4; ++ni) {
            const int col = cbase + ni * 8;
            #pragma unroll
            for (int half = 0; half < 2; ++half) {
                const int row = rbase + mi * 16 + half * 8;
                float v0 = acc[mi][ni][half * 2 + 0];
                float v1 = acc[mi][ni][half * 2 + 1];
                if (EPI == 0) {
                    *(float2*)(C + (size_t)row * N + col) = {v0, v1};
                } else if (EPI == 1) {
                    const float2 rv = *(const float2*)(R + (size_t)row * N + col);
                    v0 += bias[col]     + rv.x;
                    v1 += bias[col + 1] + rv.y;
                    *(float2*)(C + (size_t)row * N + col) = {v0, v1};
                } else {
                    float t0 = v0 + bias[col];
                    float t1 = v1 + bias[col + 1];
                    const float g0 = 0.5f * t0 * (1.0f + erff(t0 * 0.70710678118654752f));
                    const float g1 = 0.5f * t1 * (1.0f + erff(t1 * 0.70710678118654752f));
                    __nv_bfloat16 h0, l0, h1, l1;
                    split2(g0, h0, l0);
                    split2(g1, h1, l1);
                    const size_t e = (size_t)row * N + col;
                    *reinterpret_cast<__nv_bfloat162*>(Chi + e) = {h0, h1};
                    *reinterpret_cast<__nv_bfloat162*>(Clo + e) = {l0, l1};
                }
            }
        }
    }
}

// ======================= banded attention (q-tiled, SMEM K/V) =======================
// grid (T/64, H, B), block 256. K/V band for 64 queries cached in SMEM.
#define ATT_KBYTES (192 * 64 * 4)
#define ATT_DSMEM  (2 * ATT_KBYTES + 8 * 136 * 4)

__global__ __launch_bounds__(256, 1)
void attn_kernel(const float* __restrict__ qkv,
                 __nv_bfloat16* __restrict__ ctx_h,
                 __nv_bfloat16* __restrict__ ctx_l,
                 const int* __restrict__ csp, int T) {
    extern __shared__ char dsm[];
    float* Ks = (float*)dsm;                       // [192][64]
    float* Vs = (float*)(dsm + ATT_KBYTES);        // [192][64]
    float* scb = (float*)(dsm + 2 * ATT_KBYTES);   // [8][136]

    const int cs = min(*csp, 64);
    const int tid = threadIdx.x;
    const int wid = tid >> 5;
    const int lane = tid & 31;
    const int q0 = blockIdx.x * 64;
    const int h = blockIdx.y;
    const int b = blockIdx.z;

    const int jlo = max(q0 - cs, 0);
    const int jhi = min(q0 + 63 + cs, T - 1);
    const int nk = jhi - jlo + 1;

    for (int i = tid; i < nk * 16; i += 256) {
        const int row = i >> 4, c = i & 15;
        const float4* src = (const float4*)(qkv + (size_t)(b * T + jlo + row) * (3 * DIM) + h * HDIM);
        ((float4*)Ks)[row * 16 + c] = src[c + 128];   // +DIM floats
        ((float4*)Vs)[row * 16 + c] = src[c + 256];   // +2*DIM floats
    }
    __syncthreads();

    float* sc = scb + wid * 136;
    const float scale = 0.125f;  // 1/sqrt(64)

    for (int qi = 0; qi < 8; ++qi) {
        const int t = q0 + wid * 8 + qi;
        const float2 qv = *(const float2*)(qkv + (size_t)(b * T + t) * (3 * DIM) + h * HDIM + 2 * lane);
        const int jloq = max(t - cs, 0);
        const int jhiq = min(t + cs, T - 1);
        const int base = jloq - jlo;
        const int n = jhiq - jloq + 1;

        float mx = -INFINITY;
        for (int j = 0; j < n; ++j) {
            const float2 kk = *(const float2*)(Ks + (base + j) * 64 + 2 * lane);
            float s = qv.x * kk.x + qv.y * kk.y;
            #pragma unroll
            for (int off = 16; off > 0; off >>= 1)
                s += __shfl_xor_sync(0xFFFFFFFFu, s, off);
            s *= scale;
            mx = fmaxf(mx, s);
            if (lane == 0) sc[j] = s;
        }
        __syncwarp();

        float sum = 0.0f;
        for (int i = lane; i < n; i += 32) {
            const float p = __expf(sc[i] - mx);
            sc[i] = p;
            sum += p;
        }
        #pragma unroll
        for (int off = 16; off > 0; off >>= 1)
            sum += __shfl_xor_sync(0xFFFFFFFFu, sum, off);
        const float inv = 1.0f / sum;
        __syncwarp();

        float2 acc = {0.0f, 0.0f};
        for (int j = 0; j < n; ++j) {
            const float p = sc[j];
            const float2 vv = *(const float2*)(Vs + (base + j) * 64 + 2 * lane);
            acc.x = fmaf(p, vv.x, acc.x);
            acc.y = fmaf(p, vv.y, acc.y);
        }
        const float ox = acc.x * inv, oy = acc.y * inv;
        __nv_bfloat16 hx, lx, hy, ly;
        split2(ox, hx, lx);
        split2(oy, hy, ly);
        const size_t e = (size_t)(b * T + t) * DIM + h * HDIM + 2 * lane;
        *reinterpret_cast<__nv_bfloat162*>(ctx_h + e) = {hx, hy};
        *reinterpret_cast<__nv_bfloat162*>(ctx_l + e) = {lx, ly};
        __syncwarp();
    }
}

// ======================= launcher =======================
extern "C" void kernel_launch(void* const* d_in, const int* in_sizes, int n_in,
                              void* d_out, int out_size) {
    const float* x       = (const float*)d_in[0];
    const float* norm1_w = (const float*)d_in[1];
    const float* norm2_w = (const float*)d_in[2];
    const float* w_qkv   = (const float*)d_in[3];
    const float* w_out   = (const float*)d_in[4];
    const float* b_out   = (const float*)d_in[5];
    const float* w1      = (const float*)d_in[6];
    const float* b1      = (const float*)d_in[7];
    const float* w2      = (const float*)d_in[8];
    const float* b2      = (const float*)d_in[9];
    const int*   cs      = (const int*)d_in[10];
    float*       out     = (float*)d_out;

    const int BT = in_sizes[0] / DIM;   // 8192
    const int T  = T_SEQ;
    const int B  = BT / T;

    __nv_bfloat16 *wqkvTh, *wqkvTl, *woutTh, *woutTl, *w1Th, *w1Tl, *w2Th, *w2Tl;
    __nv_bfloat16 *xnh, *xnl, *ctxh, *ctxl, *hh, *hl;
    float *qkv, *x1;
    cudaGetSymbolAddress((void**)&wqkvTh, g_wqkvT_h);
    cudaGetSymbolAddress((void**)&wqkvTl, g_wqkvT_l);
    cudaGetSymbolAddress((void**)&woutTh, g_woutT_h);
    cudaGetSymbolAddress((void**)&woutTl, g_woutT_l);
    cudaGetSymbolAddress((void**)&w1Th,   g_w1T_h);
    cudaGetSymbolAddress((void**)&w1Tl,   g_w1T_l);
    cudaGetSymbolAddress((void**)&w2Th,   g_w2T_h);
    cudaGetSymbolAddress((void**)&w2Tl,   g_w2T_l);
    cudaGetSymbolAddress((void**)&xnh,    g_xn_h);
    cudaGetSymbolAddress((void**)&xnl,    g_xn_l);
    cudaGetSymbolAddress((void**)&ctxh,   g_ctx_h);
    cudaGetSymbolAddress((void**)&ctxl,   g_ctx_l);
    cudaGetSymbolAddress((void**)&hh,     g_hh);
    cudaGetSymbolAddress((void**)&hl,     g_hl);
    cudaGetSymbolAddress((void**)&qkv,    g_qkv);
    cudaGetSymbolAddress((void**)&x1,     g_x1);

    cudaFuncSetAttribute(gemm_mma<0>, cudaFuncAttributeMaxDynamicSharedMemorySize, GEMM_DSMEM);
    cudaFuncSetAttribute(gemm_mma<1>, cudaFuncAttributeMaxDynamicSharedMemorySize, GEMM_DSMEM);
    cudaFuncSetAttribute(gemm_mma<2>, cudaFuncAttributeMaxDynamicSharedMemorySize, GEMM_DSMEM);
    cudaFuncSetAttribute(attn_kernel, cudaFuncAttributeMaxDynamicSharedMemorySize, ATT_DSMEM);

    const dim3 wb(32, 8);
    wprep_kernel<<<dim3((3 * DIM) / 32, DIM / 32), wb>>>(w_qkv, wqkvTh, wqkvTl, DIM, 3 * DIM);
    wprep_kernel<<<dim3(DIM / 32, DIM / 32), wb>>>(w_out, woutTh, woutTl, DIM, DIM);
    wprep_kernel<<<dim3(FFN_DIM / 32, DIM / 32), wb>>>(w1, w1Th, w1Tl, DIM, FFN_DIM);
    wprep_kernel<<<dim3(DIM / 32, FFN_DIM / 32), wb>>>(w2, w2Th, w2Tl, FFN_DIM, DIM);

    // 1. xn = rmsnorm(x, norm1_w) -> hi/lo
    rmsnorm_split_kernel<<<BT, 128>>>(x, norm1_w, xnh, xnl);
    // 2. qkv = xn @ w_qkv (fp32 out)
    gemm_mma<0><<<dim3((3 * DIM) / 128, BT / 128), 256, GEMM_DSMEM>>>(
        xnh, xnl, wqkvTh, wqkvTl, nullptr, nullptr, qkv, nullptr, nullptr, BT, 3 * DIM, DIM);
    // 3. banded attention -> ctx hi/lo
    attn_kernel<<<dim3(T / 64, NHEAD, B), 256, ATT_DSMEM>>>(qkv, ctxh, ctxl, cs, T);
    // 4. x1 = x + ctx @ w_out + b_out
    gemm_mma<1><<<dim3(DIM / 128, BT / 128), 256, GEMM_DSMEM>>>(
        ctxh, ctxl, woutTh, woutTl, b_out, x, x1, nullptr, nullptr, BT, DIM, DIM);
    // 5. xn = rmsnorm(x1, norm2_w) -> hi/lo
    rmsnorm_split_kernel<<<BT, 128>>>(x1, norm2_w, xnh, xnl);
    // 6. h = gelu(xn @ w1 + b1) -> hi/lo bf16
    gemm_mma<2><<<dim3(FFN_DIM / 128, BT / 128), 256, GEMM_DSMEM>>>(
        xnh, xnl, w1Th, w1Tl, b1, nullptr, nullptr, hh, hl, BT, FFN_DIM, DIM);
    // 7. out = x1 + h @ w2 + b2
    gemm_mma<1><<<dim3(DIM / 128, BT / 128), 256, GEMM_DSMEM>>>(
        hh, hl, w2Th, w2Tl, b2, x1, out, nullptr, nullptr, BT, DIM, FFN_DIM);
}

// round 8
// speedup vs baseline: 2.7257x; 1.4807x over previous
#include <cuda_runtime.h>
#include <cuda_fp16.h>
#include <math.h>
#include <stdint.h>

// Problem shape (fixed by the dataset): B=4, T=2048, D=512, H=8, Hd=64, FFN=2048
#define T_SEQ   2048
#define DIM     512
#define NHEAD   8
#define HDIM    64
#define FFN_DIM 2048
#define MAX_BT  8192

// ======================= helpers =======================
__device__ __forceinline__ uint32_t smem_u32(const void* p) {
    uint32_t a;
    asm("{ .reg .u64 t; cvta.to.shared.u64 t, %1; cvt.u32.u64 %0, t; }" : "=r"(a) : "l"(p));
    return a;
}
__device__ __forceinline__ void cp16(uint32_t s, const void* g) {
    asm volatile("cp.async.ca.shared.global [%0], [%1], 16;" :: "r"(s), "l"(g));
}
#define CP_COMMIT() asm volatile("cp.async.commit_group;" ::: "memory")
#define CP_WAIT1()  asm volatile("cp.async.wait_group 1;" ::: "memory")

__device__ __forceinline__ void ldsm4(uint32_t* r, uint32_t addr) {
    asm volatile("ldmatrix.sync.aligned.m8n8.x4.shared.b16 {%0,%1,%2,%3}, [%4];"
        : "=r"(r[0]), "=r"(r[1]), "=r"(r[2]), "=r"(r[3]) : "r"(addr));
}
// main term: f16 inputs, f32 accumulate
__device__ __forceinline__ void mma_f32(float* c, const uint32_t* a, const uint32_t* b) {
    asm volatile(
        "mma.sync.aligned.m16n8k16.row.col.f32.f16.f16.f32 "
        "{%0,%1,%2,%3}, {%4,%5,%6,%7}, {%8,%9}, {%0,%1,%2,%3};"
        : "+f"(c[0]), "+f"(c[1]), "+f"(c[2]), "+f"(c[3])
        : "r"(a[0]), "r"(a[1]), "r"(a[2]), "r"(a[3]), "r"(b[0]), "r"(b[1]));
}
// correction terms: f16 inputs, f16 accumulate (2 packed regs)
__device__ __forceinline__ void mma_f16(uint32_t* c, const uint32_t* a, const uint32_t* b) {
    asm volatile(
        "mma.sync.aligned.m16n8k16.row.col.f16.f16.f16.f16 "
        "{%0,%1}, {%2,%3,%4,%5}, {%6,%7}, {%0,%1};"
        : "+r"(c[0]), "+r"(c[1])
        : "r"(a[0]), "r"(a[1]), "r"(a[2]), "r"(a[3]), "r"(b[0]), "r"(b[1]));
}
__device__ __forceinline__ void split2(float f, __half& h, __half& l) {
    h = __float2half_rn(f);
    l = __float2half_rn(f - __half2float(h));
}

// ======================= scratch =======================
__device__ __half g_wqkvT_h[3 * DIM * DIM], g_wqkvT_l[3 * DIM * DIM];
__device__ __half g_woutT_h[DIM * DIM],     g_woutT_l[DIM * DIM];
__device__ __half g_w1T_h[FFN_DIM * DIM],   g_w1T_l[FFN_DIM * DIM];
__device__ __half g_w2T_h[DIM * FFN_DIM],   g_w2T_l[DIM * FFN_DIM];
__device__ __half g_xn_h[MAX_BT * DIM],     g_xn_l[MAX_BT * DIM];
__device__ __half g_ctx_h[MAX_BT * DIM],    g_ctx_l[MAX_BT * DIM];
__device__ __half g_hh[MAX_BT * FFN_DIM],   g_hl[MAX_BT * FFN_DIM];
__device__ float g_qkv[MAX_BT * 3 * DIM];
__device__ float g_x1[MAX_BT * DIM];

// ======================= weight prep: W[K][N] -> WT hi/lo [N][K] =======================
__global__ void wprep_kernel(const float* __restrict__ W,
                             __half* __restrict__ Th,
                             __half* __restrict__ Tl,
                             int K, int N) {
    __shared__ float t[32][33];
    const int n0 = blockIdx.x * 32, k0 = blockIdx.y * 32;
    const int tx = threadIdx.x, ty = threadIdx.y;
    #pragma unroll
    for (int i = 0; i < 4; ++i)
        t[ty + i * 8][tx] = W[(size_t)(k0 + ty + i * 8) * N + n0 + tx];
    __syncthreads();
    #pragma unroll
    for (int i = 0; i < 4; ++i) {
        const float v = t[tx][ty + i * 8];
        __half h, l;
        split2(v, h, l);
        const size_t o = (size_t)(n0 + ty + i * 8) * K + k0 + tx;
        Th[o] = h;
        Tl[o] = l;
    }
}

// ======================= rmsnorm -> f16 hi/lo =======================
__global__ void rmsnorm_split_kernel(const float* __restrict__ x,
                                     const float* __restrict__ w,
                                     __half* __restrict__ yh,
                                     __half* __restrict__ yl) {
    const int row = blockIdx.x;
    const int tid = threadIdx.x;  // 128
    const float4 v = reinterpret_cast<const float4*>(x + (size_t)row * DIM)[tid];
    float ss = v.x * v.x + v.y * v.y + v.z * v.z + v.w * v.w;
    #pragma unroll
    for (int off = 16; off > 0; off >>= 1)
        ss += __shfl_xor_sync(0xFFFFFFFFu, ss, off);
    __shared__ float red[4];
    const int warp = tid >> 5, lane = tid & 31;
    if (lane == 0) red[warp] = ss;
    __syncthreads();
    const float r = rsqrtf((red[0] + red[1] + red[2] + red[3]) * (1.0f / DIM) + 1e-6f);
    const float4 wv = reinterpret_cast<const float4*>(w)[tid];
    float o[4] = {v.x * r * wv.x, v.y * r * wv.y, v.z * r * wv.z, v.w * r * wv.w};
    __half h[4], l[4];
    #pragma unroll
    for (int j = 0; j < 4; ++j) split2(o[j], h[j], l[j]);
    const size_t e = (size_t)row * DIM + tid * 4;
    *reinterpret_cast<__half2*>(yh + e)     = __halves2half2(h[0], h[1]);
    *reinterpret_cast<__half2*>(yh + e + 2) = __halves2half2(h[2], h[3]);
    *reinterpret_cast<__half2*>(yl + e)     = __halves2half2(l[0], l[1]);
    *reinterpret_cast<__half2*>(yl + e + 2) = __halves2half2(l[2], l[3]);
}

// ======================= mma.sync GEMM (f16 split, f16-acc corrections) ==============
// C[M,N] = sum_k A[M,K]*B^T[N,K]; A,B pre-split f16 hi/lo, K-major rows.
// 128x128 tile, 8 warps (64x32), K-slab 64, 2-stage cp.async (147KB smem, occ 1).
// Main: Ah*Bh f32-acc. Corrections: Ah*Bl + Al*Bh f16-acc.
// SMEM row stride 72 b16 units (144B) -> conflict-free cp.async + ldmatrix.
// EPI: 0 fp32 C; 1 +bias+resid fp32 C; 2 +bias, gelu -> f16 hi/lo
#define PADK   72
#define MATB   (128 * 144)           // 18432 B per matrix tile
#define STAGEB (4 * MATB)            // 73728
#define GEMM_DSMEM (2 * STAGEB)      // 147456

template <int EPI>
__global__ __launch_bounds__(256)
void gemm_mma(const __half* __restrict__ Ahi, const __half* __restrict__ Alo,
              const __half* __restrict__ Bhi, const __half* __restrict__ Blo,
              const float* __restrict__ bias, const float* __restrict__ R,
              float* __restrict__ C,
              __half* __restrict__ Chi, __half* __restrict__ Clo,
              int M, int N, int K) {
    extern __shared__ char dsm[];
    const uint32_t sm0 = smem_u32(dsm);
    const int tid = threadIdx.x;
    const int wid = tid >> 5;
    const int lane = tid & 31;
    const int wm = wid & 1;
    const int wn = wid >> 1;
    const int bm = blockIdx.y * 128;
    const int bn = blockIdx.x * 128;

    const int NS = K / 64;

    auto load_slab = [&](int s) {
        const uint32_t st = sm0 + (uint32_t)(s & 1) * STAGEB;
        const int k0 = s * 64;
        #pragma unroll
        for (int i = 0; i < 4; ++i) {
            const int idx = tid + i * 256;        // 0..1023
            const int row = idx >> 3;             // 0..127
            const int c   = idx & 7;              // 0..7
            const uint32_t so = (uint32_t)(row * 144 + c * 16);
            const size_t gA = (size_t)(bm + row) * K + k0 + c * 8;
            const size_t gB = (size_t)(bn + row) * K + k0 + c * 8;
            cp16(st + 0 * MATB + so, Ahi + gA);
            cp16(st + 1 * MATB + so, Alo + gA);
            cp16(st + 2 * MATB + so, Bhi + gB);
            cp16(st + 3 * MATB + so, Blo + gB);
        }
    };

    float acc[4][4][4] = {};
    uint32_t corr[4][4][2] = {};

    load_slab(0); CP_COMMIT();
    if (NS > 1) { load_slab(1); }
    CP_COMMIT();

    const uint32_t aRow = (uint32_t)(wm * 64 + (lane & 15));
    const uint32_t aKo  = (uint32_t)((lane >> 4) * 8);
    const uint32_t bRow = (uint32_t)(wn * 32 + (lane & 7) + ((lane >> 4) << 3));
    const uint32_t bKo  = (uint32_t)(((lane >> 3) & 1) * 8);

    for (int s = 0; s < NS; ++s) {
        CP_WAIT1();
        __syncthreads();
        const uint32_t st = sm0 + (uint32_t)(s & 1) * STAGEB;

        #pragma unroll
        for (int kk = 0; kk < 64; kk += 16) {
            uint32_t bh[2][4], bl[2][4];
            #pragma unroll
            for (int g = 0; g < 2; ++g) {
                const uint32_t off = ((bRow + g * 16) * PADK + kk + bKo) * 2;
                ldsm4(bh[g], st + 2 * MATB + off);
                ldsm4(bl[g], st + 3 * MATB + off);
            }
            #pragma unroll
            for (int mi = 0; mi < 4; ++mi) {
                uint32_t ah[4], al[4];
                const uint32_t off = ((aRow + mi * 16) * PADK + kk + aKo) * 2;
                ldsm4(ah, st + 0 * MATB + off);
                ldsm4(al, st + 1 * MATB + off);
                #pragma unroll
                for (int ni = 0; ni < 4; ++ni) {
                    const int g = ni >> 1, sub = (ni & 1) * 2;
                    mma_f32(acc[mi][ni], ah, &bh[g][sub]);
                    mma_f16(corr[mi][ni], ah, &bl[g][sub]);
                    mma_f16(corr[mi][ni], al, &bh[g][sub]);
                }
            }
        }
        __syncthreads();
        if (s + 2 < NS) load_slab(s + 2);
        CP_COMMIT();
    }

    // epilogue
    const int cbase = bn + wn * 32 + (lane & 3) * 2;
    const int rbase = bm + wm * 64 + (lane >> 2);
    #pragma unroll
    for (int mi = 0; mi < 4; ++mi) {
        #pragma unroll
        for (int ni = 0; ni < 4; ++ni) {
            const int col = cbase + ni * 8;
            #pragma unroll
            for (int half = 0; half < 2; ++half) {
                const int row = rbase + mi * 16 + half * 8;
                const float2 cv = __half22float2(*reinterpret_cast<__half2*>(&corr[mi][ni][half]));
                float v0 = acc[mi][ni][half * 2 + 0] + cv.x;
                float v1 = acc[mi][ni][half * 2 + 1] + cv.y;
                if (EPI == 0) {
                    *(float2*)(C + (size_t)row * N + col) = {v0, v1};
                } else if (EPI == 1) {
                    const float2 rv = *(const float2*)(R + (size_t)row * N + col);
                    v0 += bias[col]     + rv.x;
                    v1 += bias[col + 1] + rv.y;
                    *(float2*)(C + (size_t)row * N + col) = {v0, v1};
                } else {
                    float t0 = v0 + bias[col];
                    float t1 = v1 + bias[col + 1];
                    const float g0 = 0.5f * t0 * (1.0f + erff(t0 * 0.70710678118654752f));
                    const float g1 = 0.5f * t1 * (1.0f + erff(t1 * 0.70710678118654752f));
                    __half h0, l0, h1, l1;
                    split2(g0, h0, l0);
                    split2(g1, h1, l1);
                    const size_t e = (size_t)row * N + col;
                    *reinterpret_cast<__half2*>(Chi + e) = __halves2half2(h0, h1);
                    *reinterpret_cast<__half2*>(Clo + e) = __halves2half2(l0, l1);
                }
            }
        }
    }
}

// ======================= banded attention (shfl-free scores) =======================
// grid (T/64, H, B), block 256 (8 warps, 8 queries each).
// SMEM: Ks[192][65] (pad65 -> conflict-free lane-per-key rows), Vs[192][66],
//       Qs[64][64], sc[8][136].
#define AT_NK   192
#define KS_PAD  65
#define VS_PAD  66
#define KS_OFF  0
#define VS_OFF  (AT_NK * KS_PAD * 4)                    // 49920
#define QS_OFF  (VS_OFF + AT_NK * VS_PAD * 4)           // 100608
#define SC_OFF  (QS_OFF + 64 * 64 * 4)                  // 116992
#define ATT_DSMEM (SC_OFF + 8 * 136 * 4)                // 121344

__global__ __launch_bounds__(256, 1)
void attn_kernel(const float* __restrict__ qkv,
                 __half* __restrict__ ctx_h,
                 __half* __restrict__ ctx_l,
                 const int* __restrict__ csp, int T) {
    extern __shared__ char dsm[];
    float* Ks  = (float*)(dsm + KS_OFF);
    float* Vs  = (float*)(dsm + VS_OFF);
    float* Qs  = (float*)(dsm + QS_OFF);
    float* scb = (float*)(dsm + SC_OFF);

    const int cs = min(*csp, 64);
    const int tid = threadIdx.x;
    const int wid = tid >> 5;
    const int lane = tid & 31;
    const int q0 = blockIdx.x * 64;
    const int h = blockIdx.y;
    const int b = blockIdx.z;

    const int jlo = max(q0 - cs, 0);
    const int jhi = min(q0 + 63 + cs, T - 1);
    const int nk = jhi - jlo + 1;

    // load K/V band (padded rows) + Q tile
    for (int i = tid; i < nk * 16; i += 256) {
        const int row = i >> 4, c = i & 15;
        const float4* src = (const float4*)(qkv + (size_t)(b * T + jlo + row) * (3 * DIM) + h * HDIM);
        const float4 kv = src[c + 128];   // K at +DIM
        const float4 vv = src[c + 256];   // V at +2*DIM
        float* kr = Ks + row * KS_PAD + c * 4;
        kr[0] = kv.x; kr[1] = kv.y; kr[2] = kv.z; kr[3] = kv.w;
        float* vr = Vs + row * VS_PAD + c * 4;
        *(float2*)(vr)     = {vv.x, vv.y};
        *(float2*)(vr + 2) = {vv.z, vv.w};
    }
    for (int i = tid; i < 64 * 16; i += 256) {
        const int row = i >> 4, c = i & 15;
        const float4* src = (const float4*)(qkv + (size_t)(b * T + q0 + row) * (3 * DIM) + h * HDIM);
        *(float4*)(Qs + row * 64 + c * 4) = src[c];
    }
    __syncthreads();

    float* sc = scb + wid * 136;
    const float scale = 0.125f;  // 1/sqrt(64)

    for (int qi = 0; qi < 8; ++qi) {
        const int qloc = wid * 8 + qi;
        const int t = q0 + qloc;
        const float* qrow = Qs + qloc * 64;
        const int jloq = max(t - cs, 0);
        const int jhiq = min(t + cs, T - 1);
        const int base = jloq - jlo;
        const int n = jhiq - jloq + 1;

        // pass 1: per-lane full dot products, no shuffles
        float s[5] = {0.0f, 0.0f, 0.0f, 0.0f, 0.0f};
        const float* kr[5];
        #pragma unroll
        for (int c = 0; c < 5; ++c) {
            const int j = c * 32 + lane;
            kr[c] = Ks + (size_t)min(base + j, AT_NK - 1) * KS_PAD;
        }
        #pragma unroll 8
        for (int d = 0; d < 64; ++d) {
            const float qd = qrow[d];
            #pragma unroll
            for (int c = 0; c < 5; ++c)
                s[c] = fmaf(qd, kr[c][d], s[c]);
        }
        float mx = -INFINITY;
        #pragma unroll
        for (int c = 0; c < 5; ++c) {
            const int j = c * 32 + lane;
            if (j < n) {
                s[c] *= scale;
                sc[j] = s[c];
                mx = fmaxf(mx, s[c]);
            }
        }
        #pragma unroll
        for (int off = 16; off > 0; off >>= 1)
            mx = fmaxf(mx, __shfl_xor_sync(0xFFFFFFFFu, mx, off));
        __syncwarp();

        // pass 2: exp + sum
        float sum = 0.0f;
        for (int i = lane; i < n; i += 32) {
            const float p = __expf(sc[i] - mx);
            sc[i] = p;
            sum += p;
        }
        #pragma unroll
        for (int off = 16; off > 0; off >>= 1)
            sum += __shfl_xor_sync(0xFFFFFFFFu, sum, off);
        const float inv = 1.0f / sum;
        __syncwarp();

        // pass 3: weighted V (each lane owns 2 dims)
        float2 acc = {0.0f, 0.0f};
        for (int j = 0; j < n; ++j) {
            const float p = sc[j];
            const float2 vv = *(const float2*)(Vs + (size_t)(base + j) * VS_PAD + 2 * lane);
            acc.x = fmaf(p, vv.x, acc.x);
            acc.y = fmaf(p, vv.y, acc.y);
        }
        const float ox = acc.x * inv, oy = acc.y * inv;
        __half hx, lx, hy, ly;
        split2(ox, hx, lx);
        split2(oy, hy, ly);
        const size_t e = (size_t)(b * T + t) * DIM + h * HDIM + 2 * lane;
        *reinterpret_cast<__half2*>(ctx_h + e) = __halves2half2(hx, hy);
        *reinterpret_cast<__half2*>(ctx_l + e) = __halves2half2(lx, ly);
        __syncwarp();
    }
}

// ======================= launcher =======================
extern "C" void kernel_launch(void* const* d_in, const int* in_sizes, int n_in,
                              void* d_out, int out_size) {
    const float* x       = (const float*)d_in[0];
    const float* norm1_w = (const float*)d_in[1];
    const float* norm2_w = (const float*)d_in[2];
    const float* w_qkv   = (const float*)d_in[3];
    const float* w_out   = (const float*)d_in[4];
    const float* b_out   = (const float*)d_in[5];
    const float* w1      = (const float*)d_in[6];
    const float* b1      = (const float*)d_in[7];
    const float* w2      = (const float*)d_in[8];
    const float* b2      = (const float*)d_in[9];
    const int*   cs      = (const int*)d_in[10];
    float*       out     = (float*)d_out;

    const int BT = in_sizes[0] / DIM;   // 8192
    const int T  = T_SEQ;
    const int B  = BT / T;

    __half *wqkvTh, *wqkvTl, *woutTh, *woutTl, *w1Th, *w1Tl, *w2Th, *w2Tl;
    __half *xnh, *xnl, *ctxh, *ctxl, *hh, *hl;
    float *qkv, *x1;
    cudaGetSymbolAddress((void**)&wqkvTh, g_wqkvT_h);
    cudaGetSymbolAddress((void**)&wqkvTl, g_wqkvT_l);
    cudaGetSymbolAddress((void**)&woutTh, g_woutT_h);
    cudaGetSymbolAddress((void**)&woutTl, g_woutT_l);
    cudaGetSymbolAddress((void**)&w1Th,   g_w1T_h);
    cudaGetSymbolAddress((void**)&w1Tl,   g_w1T_l);
    cudaGetSymbolAddress((void**)&w2Th,   g_w2T_h);
    cudaGetSymbolAddress((void**)&w2Tl,   g_w2T_l);
    cudaGetSymbolAddress((void**)&xnh,    g_xn_h);
    cudaGetSymbolAddress((void**)&xnl,    g_xn_l);
    cudaGetSymbolAddress((void**)&ctxh,   g_ctx_h);
    cudaGetSymbolAddress((void**)&ctxl,   g_ctx_l);
    cudaGetSymbolAddress((void**)&hh,     g_hh);
    cudaGetSymbolAddress((void**)&hl,     g_hl);
    cudaGetSymbolAddress((void**)&qkv,    g_qkv);
    cudaGetSymbolAddress((void**)&x1,     g_x1);

    cudaFuncSetAttribute(gemm_mma<0>, cudaFuncAttributeMaxDynamicSharedMemorySize, GEMM_DSMEM);
    cudaFuncSetAttribute(gemm_mma<1>, cudaFuncAttributeMaxDynamicSharedMemorySize, GEMM_DSMEM);
    cudaFuncSetAttribute(gemm_mma<2>, cudaFuncAttributeMaxDynamicSharedMemorySize, GEMM_DSMEM);
    cudaFuncSetAttribute(attn_kernel, cudaFuncAttributeMaxDynamicSharedMemorySize, ATT_DSMEM);

    const dim3 wb(32, 8);
    wprep_kernel<<<dim3((3 * DIM) / 32, DIM / 32), wb>>>(w_qkv, wqkvTh, wqkvTl, DIM, 3 * DIM);
    wprep_kernel<<<dim3(DIM / 32, DIM / 32), wb>>>(w_out, woutTh, woutTl, DIM, DIM);
    wprep_kernel<<<dim3(FFN_DIM / 32, DIM / 32), wb>>>(w1, w1Th, w1Tl, DIM, FFN_DIM);
    wprep_kernel<<<dim3(DIM / 32, FFN_DIM / 32), wb>>>(w2, w2Th, w2Tl, FFN_DIM, DIM);

    // 1. xn = rmsnorm(x, norm1_w) -> hi/lo
    rmsnorm_split_kernel<<<BT, 128>>>(x, norm1_w, xnh, xnl);
    // 2. qkv = xn @ w_qkv (fp32 out)
    gemm_mma<0><<<dim3((3 * DIM) / 128, BT / 128), 256, GEMM_DSMEM>>>(
        xnh, xnl, wqkvTh, wqkvTl, nullptr, nullptr, qkv, nullptr, nullptr, BT, 3 * DIM, DIM);
    // 3. banded attention -> ctx hi/lo
    attn_kernel<<<dim3(T / 64, NHEAD, B), 256, ATT_DSMEM>>>(qkv, ctxh, ctxl, cs, T);
    // 4. x1 = x + ctx @ w_out + b_out
    gemm_mma<1><<<dim3(DIM / 128, BT / 128), 256, GEMM_DSMEM>>>(
        ctxh, ctxl, woutTh, woutTl, b_out, x, x1, nullptr, nullptr, BT, DIM, DIM);
    // 5. xn = rmsnorm(x1, norm2_w) -> hi/lo
    rmsnorm_split_kernel<<<BT, 128>>>(x1, norm2_w, xnh, xnl);
    // 6. h = gelu(xn @ w1 + b1) -> hi/lo f16
    gemm_mma<2><<<dim3(FFN_DIM / 128, BT / 128), 256, GEMM_DSMEM>>>(
        xnh, xnl, w1Th, w1Tl, b1, nullptr, nullptr, hh, hl, BT, FFN_DIM, DIM);
    // 7. out = x1 + h @ w2 + b2
    gemm_mma<1><<<dim3(DIM / 128, BT / 128), 256, GEMM_DSMEM>>>(
        hh, hl, w2Th, w2Tl, b2, x1, out, nullptr, nullptr, BT, DIM, FFN_DIM);
}

// round 10
// speedup vs baseline: 3.2365x; 1.1874x over previous
#include <cuda_runtime.h>
#include <cuda_fp16.h>
#include <math.h>
#include <stdint.h>

// Problem shape (fixed by the dataset): B=4, T=2048, D=512, H=8, Hd=64, FFN=2048
#define T_SEQ   2048
#define DIM     512
#define NHEAD   8
#define HDIM    64
#define FFN_DIM 2048
#define MAX_BT  8192

// ======================= helpers =======================
__device__ __forceinline__ uint32_t smem_u32(const void* p) {
    uint32_t a;
    asm("{ .reg .u64 t; cvta.to.shared.u64 t, %1; cvt.u32.u64 %0, t; }" : "=r"(a) : "l"(p));
    return a;
}
__device__ __forceinline__ void cp16(uint32_t s, const void* g) {
    asm volatile("cp.async.ca.shared.global [%0], [%1], 16;" :: "r"(s), "l"(g));
}
#define CP_COMMIT() asm volatile("cp.async.commit_group;" ::: "memory")
#define CP_WAIT1()  asm volatile("cp.async.wait_group 1;" ::: "memory")

__device__ __forceinline__ void ldsm4(uint32_t* r, uint32_t addr) {
    asm volatile("ldmatrix.sync.aligned.m8n8.x4.shared.b16 {%0,%1,%2,%3}, [%4];"
        : "=r"(r[0]), "=r"(r[1]), "=r"(r[2]), "=r"(r[3]) : "r"(addr));
}
// main term: f16 inputs, f32 accumulate
__device__ __forceinline__ void mma_f32(float* c, const uint32_t* a, const uint32_t* b) {
    asm volatile(
        "mma.sync.aligned.m16n8k16.row.col.f32.f16.f16.f32 "
        "{%0,%1,%2,%3}, {%4,%5,%6,%7}, {%8,%9}, {%0,%1,%2,%3};"
        : "+f"(c[0]), "+f"(c[1]), "+f"(c[2]), "+f"(c[3])
        : "r"(a[0]), "r"(a[1]), "r"(a[2]), "r"(a[3]), "r"(b[0]), "r"(b[1]));
}
// correction term: f16 inputs, f16 accumulate (2 packed regs)
__device__ __forceinline__ void mma_f16(uint32_t* c, const uint32_t* a, const uint32_t* b) {
    asm volatile(
        "mma.sync.aligned.m16n8k16.row.col.f16.f16.f16.f16 "
        "{%0,%1}, {%2,%3,%4,%5}, {%6,%7}, {%0,%1};"
        : "+r"(c[0]), "+r"(c[1])
        : "r"(a[0]), "r"(a[1]), "r"(a[2]), "r"(a[3]), "r"(b[0]), "r"(b[1]));
}
__device__ __forceinline__ void split2(float f, __half& h, __half& l) {
    h = __float2half_rn(f);
    l = __float2half_rn(f - __half2float(h));
}

// ======================= scratch =======================
__device__ __half g_wqkvT_h[3 * DIM * DIM], g_wqkvT_l[3 * DIM * DIM];
__device__ __half g_woutT_h[DIM * DIM],     g_woutT_l[DIM * DIM];
__device__ __half g_w1T_h[FFN_DIM * DIM],   g_w1T_l[FFN_DIM * DIM];
__device__ __half g_w2T_h[DIM * FFN_DIM],   g_w2T_l[DIM * FFN_DIM];
__device__ __half g_xn[MAX_BT * DIM];        // activations: single f16
__device__ __half g_ctx[MAX_BT * DIM];
__device__ __half g_hh[MAX_BT * FFN_DIM];
__device__ float g_qkv[MAX_BT * 3 * DIM];
__device__ float g_x1[MAX_BT * DIM];

// ======================= weight prep: W[K][N] -> WT hi/lo [N][K] =======================
__global__ void wprep_kernel(const float* __restrict__ W,
                             __half* __restrict__ Th,
                             __half* __restrict__ Tl,
                             int K, int N) {
    __shared__ float t[32][33];
    const int n0 = blockIdx.x * 32, k0 = blockIdx.y * 32;
    const int tx = threadIdx.x, ty = threadIdx.y;
    #pragma unroll
    for (int i = 0; i < 4; ++i)
        t[ty + i * 8][tx] = W[(size_t)(k0 + ty + i * 8) * N + n0 + tx];
    __syncthreads();
    #pragma unroll
    for (int i = 0; i < 4; ++i) {
        const float v = t[tx][ty + i * 8];
        __half h, l;
        split2(v, h, l);
        const size_t o = (size_t)(n0 + ty + i * 8) * K + k0 + tx;
        Th[o] = h;
        Tl[o] = l;
    }
}

// ======================= rmsnorm -> f16 =======================
__global__ void rmsnorm_h_kernel(const float* __restrict__ x,
                                 const float* __restrict__ w,
                                 __half* __restrict__ y) {
    const int row = blockIdx.x;
    const int tid = threadIdx.x;  // 128
    const float4 v = reinterpret_cast<const float4*>(x + (size_t)row * DIM)[tid];
    float ss = v.x * v.x + v.y * v.y + v.z * v.z + v.w * v.w;
    #pragma unroll
    for (int off = 16; off > 0; off >>= 1)
        ss += __shfl_xor_sync(0xFFFFFFFFu, ss, off);
    __shared__ float red[4];
    const int warp = tid >> 5, lane = tid & 31;
    if (lane == 0) red[warp] = ss;
    __syncthreads();
    const float r = rsqrtf((red[0] + red[1] + red[2] + red[3]) * (1.0f / DIM) + 1e-6f);
    const float4 wv = reinterpret_cast<const float4*>(w)[tid];
    const size_t e = (size_t)row * DIM + tid * 4;
    *reinterpret_cast<__half2*>(y + e) =
        __floats2half2_rn(v.x * r * wv.x, v.y * r * wv.y);
    *reinterpret_cast<__half2*>(y + e + 2) =
        __floats2half2_rn(v.z * r * wv.z, v.w * r * wv.w);
}

// ======================= mma.sync GEMM (A single f16, B hi/lo) ==============
// C[M,N] = sum_k A[M,K]*B^T[N,K]. Main: A*Bh f32-acc. Correction: A*Bl f16-acc.
// 128x128 tile, 8 warps (64x32), K-slab 64, 2-stage cp.async, 2 CTAs/SM.
// SMEM row stride 72 b16 units (144B).
// EPI: 0 fp32 C; 1 +bias+resid fp32 C; 2 +bias, gelu -> f16 C
#define PADK   72
#define MATB   (128 * 144)           // 18432 B per matrix tile
#define STAGEB (3 * MATB)            // A, Bh, Bl = 55296
#define GEMM_DSMEM (2 * STAGEB)      // 110592

template <int EPI>
__global__ __launch_bounds__(256, 2)
void gemm_mma(const __half* __restrict__ A,
              const __half* __restrict__ Bhi, const __half* __restrict__ Blo,
              const float* __restrict__ bias, const float* __restrict__ R,
              float* __restrict__ C, __half* __restrict__ Ch,
              int M, int N, int K) {
    extern __shared__ char dsm[];
    const uint32_t sm0 = smem_u32(dsm);
    const int tid = threadIdx.x;
    const int wid = tid >> 5;
    const int lane = tid & 31;
    const int wm = wid & 1;
    const int wn = wid >> 1;
    const int bm = blockIdx.y * 128;
    const int bn = blockIdx.x * 128;

    const int NS = K / 64;

    auto load_slab = [&](int s) {
        const uint32_t st = sm0 + (uint32_t)(s & 1) * STAGEB;
        const int k0 = s * 64;
        #pragma unroll
        for (int i = 0; i < 4; ++i) {
            const int idx = tid + i * 256;        // 0..1023
            const int row = idx >> 3;             // 0..127
            const int c   = idx & 7;              // 0..7
            const uint32_t so = (uint32_t)(row * 144 + c * 16);
            const size_t gA = (size_t)(bm + row) * K + k0 + c * 8;
            const size_t gB = (size_t)(bn + row) * K + k0 + c * 8;
            cp16(st + 0 * MATB + so, A   + gA);
            cp16(st + 1 * MATB + so, Bhi + gB);
            cp16(st + 2 * MATB + so, Blo + gB);
        }
    };

    float acc[4][4][4] = {};
    uint32_t corr[4][4][2] = {};

    load_slab(0); CP_COMMIT();
    if (NS > 1) { load_slab(1); }
    CP_COMMIT();

    const uint32_t aRow = (uint32_t)(wm * 64 + (lane & 15));
    const uint32_t aKo  = (uint32_t)((lane >> 4) * 8);
    const uint32_t bRow = (uint32_t)(wn * 32 + (lane & 7) + ((lane >> 4) << 3));
    const uint32_t bKo  = (uint32_t)(((lane >> 3) & 1) * 8);

    for (int s = 0; s < NS; ++s) {
        CP_WAIT1();
        __syncthreads();
        const uint32_t st = sm0 + (uint32_t)(s & 1) * STAGEB;

        #pragma unroll
        for (int kk = 0; kk < 64; kk += 16) {
            uint32_t bh[2][4], bl[2][4];
            #pragma unroll
            for (int g = 0; g < 2; ++g) {
                const uint32_t off = ((bRow + g * 16) * PADK + kk + bKo) * 2;
                ldsm4(bh[g], st + 1 * MATB + off);
                ldsm4(bl[g], st + 2 * MATB + off);
            }
            #pragma unroll
            for (int mi = 0; mi < 4; ++mi) {
                uint32_t ah[4];
                const uint32_t off = ((aRow + mi * 16) * PADK + kk + aKo) * 2;
                ldsm4(ah, st + 0 * MATB + off);
                #pragma unroll
                for (int ni = 0; ni < 4; ++ni) {
                    const int g = ni >> 1, sub = (ni & 1) * 2;
                    mma_f32(acc[mi][ni], ah, &bh[g][sub]);
                    mma_f16(corr[mi][ni], ah, &bl[g][sub]);
                }
            }
        }
        __syncthreads();
        if (s + 2 < NS) load_slab(s + 2);
        CP_COMMIT();
    }

    // epilogue
    const int cbase = bn + wn * 32 + (lane & 3) * 2;
    const int rbase = bm + wm * 64 + (lane >> 2);
    #pragma unroll
    for (int mi = 0; mi < 4; ++mi) {
        #pragma unroll
        for (int ni = 0; ni < 4; ++ni) {
            const int col = cbase + ni * 8;
            #pragma unroll
            for (int half = 0; half < 2; ++half) {
                const int row = rbase + mi * 16 + half * 8;
                const float2 cv = __half22float2(*reinterpret_cast<__half2*>(&corr[mi][ni][half]));
                float v0 = acc[mi][ni][half * 2 + 0] + cv.x;
                float v1 = acc[mi][ni][half * 2 + 1] + cv.y;
                if (EPI == 0) {
                    *(float2*)(C + (size_t)row * N + col) = {v0, v1};
                } else if (EPI == 1) {
                    const float2 rv = *(const float2*)(R + (size_t)row * N + col);
                    v0 += bias[col]     + rv.x;
                    v1 += bias[col + 1] + rv.y;
                    *(float2*)(C + (size_t)row * N + col) = {v0, v1};
                } else {
                    const float t0 = v0 + bias[col];
                    const float t1 = v1 + bias[col + 1];
                    const float g0 = 0.5f * t0 * (1.0f + erff(t0 * 0.70710678118654752f));
                    const float g1 = 0.5f * t1 * (1.0f + erff(t1 * 0.70710678118654752f));
                    *reinterpret_cast<__half2*>(Ch + (size_t)row * N + col) =
                        __floats2half2_rn(g0, g1);
                }
            }
        }
    }
}

// ======================= banded attention (shfl-free scores) =======================
// grid (T/64, H, B), block 256 (8 warps, 8 queries each).
#define AT_NK   192
#define KS_PAD  65
#define VS_PAD  66
#define KS_OFF  0
#define VS_OFF  (AT_NK * KS_PAD * 4)                    // 49920
#define QS_OFF  (VS_OFF + AT_NK * VS_PAD * 4)           // 100608
#define SC_OFF  (QS_OFF + 64 * 64 * 4)                  // 116992
#define ATT_DSMEM (SC_OFF + 8 * 136 * 4)                // 121344

__global__ __launch_bounds__(256, 1)
void attn_kernel(const float* __restrict__ qkv,
                 __half* __restrict__ ctx,
                 const int* __restrict__ csp, int T) {
    extern __shared__ char dsm[];
    float* Ks  = (float*)(dsm + KS_OFF);
    float* Vs  = (float*)(dsm + VS_OFF);
    float* Qs  = (float*)(dsm + QS_OFF);
    float* scb = (float*)(dsm + SC_OFF);

    const int cs = min(*csp, 64);
    const int tid = threadIdx.x;
    const int wid = tid >> 5;
    const int lane = tid & 31;
    const int q0 = blockIdx.x * 64;
    const int h = blockIdx.y;
    const int b = blockIdx.z;

    const int jlo = max(q0 - cs, 0);
    const int jhi = min(q0 + 63 + cs, T - 1);
    const int nk = jhi - jlo + 1;

    for (int i = tid; i < nk * 16; i += 256) {
        const int row = i >> 4, c = i & 15;
        const float4* src = (const float4*)(qkv + (size_t)(b * T + jlo + row) * (3 * DIM) + h * HDIM);
        const float4 kv = src[c + 128];
        const float4 vv = src[c + 256];
        float* kr = Ks + row * KS_PAD + c * 4;
        kr[0] = kv.x; kr[1] = kv.y; kr[2] = kv.z; kr[3] = kv.w;
        float* vr = Vs + row * VS_PAD + c * 4;
        *(float2*)(vr)     = {vv.x, vv.y};
        *(float2*)(vr + 2) = {vv.z, vv.w};
    }
    for (int i = tid; i < 64 * 16; i += 256) {
        const int row = i >> 4, c = i & 15;
        const float4* src = (const float4*)(qkv + (size_t)(b * T + q0 + row) * (3 * DIM) + h * HDIM);
        *(float4*)(Qs + row * 64 + c * 4) = src[c];
    }
    __syncthreads();

    float* sc = scb + wid * 136;
    const float scale = 0.125f;

    for (int qi = 0; qi < 8; ++qi) {
        const int qloc = wid * 8 + qi;
        const int t = q0 + qloc;
        const float* qrow = Qs + qloc * 64;
        const int jloq = max(t - cs, 0);
        const int jhiq = min(t + cs, T - 1);
        const int base = jloq - jlo;
        const int n = jhiq - jloq + 1;

        float s[5] = {0.0f, 0.0f, 0.0f, 0.0f, 0.0f};
        const float* kr[5];
        #pragma unroll
        for (int c = 0; c < 5; ++c) {
            const int j = c * 32 + lane;
            kr[c] = Ks + (size_t)min(base + j, AT_NK - 1) * KS_PAD;
        }
        #pragma unroll 8
        for (int d = 0; d < 64; ++d) {
            const float qd = qrow[d];
            #pragma unroll
            for (int c = 0; c < 5; ++c)
                s[c] = fmaf(qd, kr[c][d], s[c]);
        }
        float mx = -INFINITY;
        #pragma unroll
        for (int c = 0; c < 5; ++c) {
            const int j = c * 32 + lane;
            if (j < n) {
                s[c] *= scale;
                sc[j] = s[c];
                mx = fmaxf(mx, s[c]);
            }
        }
        #pragma unroll
        for (int off = 16; off > 0; off >>= 1)
            mx = fmaxf(mx, __shfl_xor_sync(0xFFFFFFFFu, mx, off));
        __syncwarp();

        float sum = 0.0f;
        for (int i = lane; i < n; i += 32) {
            const float p = __expf(sc[i] - mx);
            sc[i] = p;
            sum += p;
        }
        #pragma unroll
        for (int off = 16; off > 0; off >>= 1)
            sum += __shfl_xor_sync(0xFFFFFFFFu, sum, off);
        const float inv = 1.0f / sum;
        __syncwarp();

        float2 acc = {0.0f, 0.0f};
        for (int j = 0; j < n; ++j) {
            const float p = sc[j];
            const float2 vv = *(const float2*)(Vs + (size_t)(base + j) * VS_PAD + 2 * lane);
            acc.x = fmaf(p, vv.x, acc.x);
            acc.y = fmaf(p, vv.y, acc.y);
        }
        *reinterpret_cast<__half2*>(ctx + (size_t)(b * T + t) * DIM + h * HDIM + 2 * lane) =
            __floats2half2_rn(acc.x * inv, acc.y * inv);
        __syncwarp();
    }
}

// ======================= launcher =======================
extern "C" void kernel_launch(void* const* d_in, const int* in_sizes, int n_in,
                              void* d_out, int out_size) {
    const float* x       = (const float*)d_in[0];
    const float* norm1_w = (const float*)d_in[1];
    const float* norm2_w = (const float*)d_in[2];
    const float* w_qkv   = (const float*)d_in[3];
    const float* w_out   = (const float*)d_in[4];
    const float* b_out   = (const float*)d_in[5];
    const float* w1      = (const float*)d_in[6];
    const float* b1      = (const float*)d_in[7];
    const float* w2      = (const float*)d_in[8];
    const float* b2      = (const float*)d_in[9];
    const int*   cs      = (const int*)d_in[10];
    float*       out     = (float*)d_out;

    const int BT = in_sizes[0] / DIM;   // 8192
    const int T  = T_SEQ;
    const int B  = BT / T;

    __half *wqkvTh, *wqkvTl, *woutTh, *woutTl, *w1Th, *w1Tl, *w2Th, *w2Tl;
    __half *xn, *ctx, *hh;
    float *qkv, *x1;
    cudaGetSymbolAddress((void**)&wqkvTh, g_wqkvT_h);
    cudaGetSymbolAddress((void**)&wqkvTl, g_wqkvT_l);
    cudaGetSymbolAddress((void**)&woutTh, g_woutT_h);
    cudaGetSymbolAddress((void**)&woutTl, g_woutT_l);
    cudaGetSymbolAddress((void**)&w1Th,   g_w1T_h);
    cudaGetSymbolAddress((void**)&w1Tl,   g_w1T_l);
    cudaGetSymbolAddress((void**)&w2Th,   g_w2T_h);
    cudaGetSymbolAddress((void**)&w2Tl,   g_w2T_l);
    cudaGetSymbolAddress((void**)&xn,     g_xn);
    cudaGetSymbolAddress((void**)&ctx,    g_ctx);
    cudaGetSymbolAddress((void**)&hh,     g_hh);
    cudaGetSymbolAddress((void**)&qkv,    g_qkv);
    cudaGetSymbolAddress((void**)&x1,     g_x1);

    cudaFuncSetAttribute(gemm_mma<0>, cudaFuncAttributeMaxDynamicSharedMemorySize, GEMM_DSMEM);
    cudaFuncSetAttribute(gemm_mma<1>, cudaFuncAttributeMaxDynamicSharedMemorySize, GEMM_DSMEM);
    cudaFuncSetAttribute(gemm_mma<2>, cudaFuncAttributeMaxDynamicSharedMemorySize, GEMM_DSMEM);
    cudaFuncSetAttribute(attn_kernel, cudaFuncAttributeMaxDynamicSharedMemorySize, ATT_DSMEM);

    const dim3 wb(32, 8);
    wprep_kernel<<<dim3((3 * DIM) / 32, DIM / 32), wb>>>(w_qkv, wqkvTh, wqkvTl, DIM, 3 * DIM);
    wprep_kernel<<<dim3(DIM / 32, DIM / 32), wb>>>(w_out, woutTh, woutTl, DIM, DIM);
    wprep_kernel<<<dim3(FFN_DIM / 32, DIM / 32), wb>>>(w1, w1Th, w1Tl, DIM, FFN_DIM);
    wprep_kernel<<<dim3(DIM / 32, FFN_DIM / 32), wb>>>(w2, w2Th, w2Tl, FFN_DIM, DIM);

    // 1. xn = rmsnorm(x, norm1_w) -> f16
    rmsnorm_h_kernel<<<BT, 128>>>(x, norm1_w, xn);
    // 2. qkv = xn @ w_qkv (fp32 out)
    gemm_mma<0><<<dim3((3 * DIM) / 128, BT / 128), 256, GEMM_DSMEM>>>(
        xn, wqkvTh, wqkvTl, nullptr, nullptr, qkv, nullptr, BT, 3 * DIM, DIM);
    // 3. banded attention -> ctx f16
    attn_kernel<<<dim3(T / 64, NHEAD, B), 256, ATT_DSMEM>>>(qkv, ctx, cs, T);
    // 4. x1 = x + ctx @ w_out + b_out
    gemm_mma<1><<<dim3(DIM / 128, BT / 128), 256, GEMM_DSMEM>>>(
        ctx, woutTh, woutTl, b_out, x, x1, nullptr, BT, DIM, DIM);
    // 5. xn = rmsnorm(x1, norm2_w) -> f16
    rmsnorm_h_kernel<<<BT, 128>>>(x1, norm2_w, xn);
    // 6. h = gelu(xn @ w1 + b1) -> f16
    gemm_mma<2><<<dim3(FFN_DIM / 128, BT / 128), 256, GEMM_DSMEM>>>(
        xn, w1Th, w1Tl, b1, nullptr, nullptr, hh, BT, FFN_DIM, DIM);
    // 7. out = x1 + h @ w2 + b2
    gemm_mma<1><<<dim3(DIM / 128, BT / 128), 256, GEMM_DSMEM>>>(
        hh, w2Th, w2Tl, b2, x1, out, nullptr, BT, DIM, FFN_DIM);
}

// round 11
// speedup vs baseline: 4.1870x; 1.2937x over previous
#include <cuda_runtime.h>
#include <cuda_fp16.h>
#include <math.h>
#include <stdint.h>

// Problem shape (fixed by the dataset): B=4, T=2048, D=512, H=8, Hd=64, FFN=2048
#define T_SEQ   2048
#define DIM     512
#define NHEAD   8
#define HDIM    64
#define FFN_DIM 2048
#define MAX_BT  8192

// ======================= helpers =======================
__device__ __forceinline__ uint32_t smem_u32(const void* p) {
    uint32_t a;
    asm("{ .reg .u64 t; cvta.to.shared.u64 t, %1; cvt.u32.u64 %0, t; }" : "=r"(a) : "l"(p));
    return a;
}
__device__ __forceinline__ void cp16(uint32_t s, const void* g) {
    asm volatile("cp.async.ca.shared.global [%0], [%1], 16;" :: "r"(s), "l"(g));
}
#define CP_COMMIT() asm volatile("cp.async.commit_group;" ::: "memory")
#define CP_WAIT2()  asm volatile("cp.async.wait_group 2;" ::: "memory")

__device__ __forceinline__ void ldsm4(uint32_t* r, uint32_t addr) {
    asm volatile("ldmatrix.sync.aligned.m8n8.x4.shared.b16 {%0,%1,%2,%3}, [%4];"
        : "=r"(r[0]), "=r"(r[1]), "=r"(r[2]), "=r"(r[3]) : "r"(addr));
}
// f16 inputs, f32 accumulate
__device__ __forceinline__ void mma_f32(float* c, const uint32_t* a, const uint32_t* b) {
    asm volatile(
        "mma.sync.aligned.m16n8k16.row.col.f32.f16.f16.f32 "
        "{%0,%1,%2,%3}, {%4,%5,%6,%7}, {%8,%9}, {%0,%1,%2,%3};"
        : "+f"(c[0]), "+f"(c[1]), "+f"(c[2]), "+f"(c[3])
        : "r"(a[0]), "r"(a[1]), "r"(a[2]), "r"(a[3]), "r"(b[0]), "r"(b[1]));
}

// ======================= scratch =======================
__device__ __half g_wqkvT[3 * DIM * DIM];
__device__ __half g_woutT[DIM * DIM];
__device__ __half g_w1T[FFN_DIM * DIM];
__device__ __half g_w2T[DIM * FFN_DIM];
__device__ __half g_xn[MAX_BT * DIM];
__device__ __half g_ctx[MAX_BT * DIM];
__device__ __half g_hh[MAX_BT * FFN_DIM];
__device__ float g_qkv[MAX_BT * 3 * DIM];
__device__ float g_x1[MAX_BT * DIM];

// ======================= weight prep: W[K][N] -> WT f16 [N][K] =======================
__global__ void wprep_kernel(const float* __restrict__ W,
                             __half* __restrict__ Th,
                             int K, int N) {
    __shared__ float t[32][33];
    const int n0 = blockIdx.x * 32, k0 = blockIdx.y * 32;
    const int tx = threadIdx.x, ty = threadIdx.y;
    #pragma unroll
    for (int i = 0; i < 4; ++i)
        t[ty + i * 8][tx] = W[(size_t)(k0 + ty + i * 8) * N + n0 + tx];
    __syncthreads();
    #pragma unroll
    for (int i = 0; i < 4; ++i)
        Th[(size_t)(n0 + ty + i * 8) * K + k0 + tx] = __float2half_rn(t[tx][ty + i * 8]);
}

// ======================= rmsnorm -> f16 =======================
__global__ void rmsnorm_h_kernel(const float* __restrict__ x,
                                 const float* __restrict__ w,
                                 __half* __restrict__ y) {
    const int row = blockIdx.x;
    const int tid = threadIdx.x;  // 128
    const float4 v = reinterpret_cast<const float4*>(x + (size_t)row * DIM)[tid];
    float ss = v.x * v.x + v.y * v.y + v.z * v.z + v.w * v.w;
    #pragma unroll
    for (int off = 16; off > 0; off >>= 1)
        ss += __shfl_xor_sync(0xFFFFFFFFu, ss, off);
    __shared__ float red[4];
    const int warp = tid >> 5, lane = tid & 31;
    if (lane == 0) red[warp] = ss;
    __syncthreads();
    const float r = rsqrtf((red[0] + red[1] + red[2] + red[3]) * (1.0f / DIM) + 1e-6f);
    const float4 wv = reinterpret_cast<const float4*>(w)[tid];
    const size_t e = (size_t)row * DIM + tid * 4;
    *reinterpret_cast<__half2*>(y + e) =
        __floats2half2_rn(v.x * r * wv.x, v.y * r * wv.y);
    *reinterpret_cast<__half2*>(y + e + 2) =
        __floats2half2_rn(v.z * r * wv.z, v.w * r * wv.w);
}

// ======================= mma.sync GEMM (plain f16, f32 acc) ==============
// C[M,N] = sum_k A[M,K]*B^T[N,K]. 128x128 tile, 8 warps (64x32), K-slab 64,
// 3-stage cp.async, 2 CTAs/SM. SMEM row stride 72 b16 units (144B).
// EPI: 0 fp32 C; 1 +bias+resid fp32 C; 2 +bias, gelu -> f16 C
#define PADK   72
#define MATB   (128 * 144)           // 18432 B per matrix tile
#define STAGEB (2 * MATB)            // A, B = 36864
#define NSTAGE 3
#define GEMM_DSMEM (NSTAGE * STAGEB) // 110592

template <int EPI>
__global__ __launch_bounds__(256, 2)
void gemm_mma(const __half* __restrict__ A, const __half* __restrict__ Bw,
              const float* __restrict__ bias, const float* __restrict__ R,
              float* __restrict__ C, __half* __restrict__ Ch,
              int M, int N, int K) {
    extern __shared__ char dsm[];
    const uint32_t sm0 = smem_u32(dsm);
    const int tid = threadIdx.x;
    const int wid = tid >> 5;
    const int lane = tid & 31;
    const int wm = wid & 1;
    const int wn = wid >> 1;
    const int bm = blockIdx.y * 128;
    const int bn = blockIdx.x * 128;

    const int NS = K / 64;

    auto load_slab = [&](int s) {
        uint32_t st = sm0;
        {
            const int b3 = s - (s / NSTAGE) * NSTAGE;
            st += (uint32_t)b3 * STAGEB;
        }
        const int k0 = s * 64;
        #pragma unroll
        for (int i = 0; i < 4; ++i) {
            const int idx = tid + i * 256;        // 0..1023
            const int row = idx >> 3;             // 0..127
            const int c   = idx & 7;              // 0..7
            const uint32_t so = (uint32_t)(row * 144 + c * 16);
            cp16(st + 0 * MATB + so, A  + (size_t)(bm + row) * K + k0 + c * 8);
            cp16(st + 1 * MATB + so, Bw + (size_t)(bn + row) * K + k0 + c * 8);
        }
    };

    float acc[4][4][4] = {};

    load_slab(0); CP_COMMIT();
    if (NS > 1) load_slab(1);
    CP_COMMIT();
    if (NS > 2) load_slab(2);
    CP_COMMIT();

    const uint32_t aRow = (uint32_t)(wm * 64 + (lane & 15));
    const uint32_t aKo  = (uint32_t)((lane >> 4) * 8);
    const uint32_t bRow = (uint32_t)(wn * 32 + (lane & 7) + ((lane >> 4) << 3));
    const uint32_t bKo  = (uint32_t)(((lane >> 3) & 1) * 8);

    int stg = 0;
    for (int s = 0; s < NS; ++s) {
        CP_WAIT2();
        __syncthreads();
        const uint32_t st = sm0 + (uint32_t)stg * STAGEB;
        if (++stg == NSTAGE) stg = 0;

        #pragma unroll
        for (int kk = 0; kk < 64; kk += 16) {
            uint32_t bf[2][4];
            #pragma unroll
            for (int g = 0; g < 2; ++g) {
                const uint32_t off = ((bRow + g * 16) * PADK + kk + bKo) * 2;
                ldsm4(bf[g], st + 1 * MATB + off);
            }
            #pragma unroll
            for (int mi = 0; mi < 4; ++mi) {
                uint32_t ah[4];
                const uint32_t off = ((aRow + mi * 16) * PADK + kk + aKo) * 2;
                ldsm4(ah, st + 0 * MATB + off);
                #pragma unroll
                for (int ni = 0; ni < 4; ++ni) {
                    const int g = ni >> 1, sub = (ni & 1) * 2;
                    mma_f32(acc[mi][ni], ah, &bf[g][sub]);
                }
            }
        }
        __syncthreads();
        if (s + NSTAGE < NS) load_slab(s + NSTAGE);
        CP_COMMIT();
    }

    // epilogue
    const int cbase = bn + wn * 32 + (lane & 3) * 2;
    const int rbase = bm + wm * 64 + (lane >> 2);
    #pragma unroll
    for (int mi = 0; mi < 4; ++mi) {
        #pragma unroll
        for (int ni = 0; ni < 4; ++ni) {
            const int col = cbase + ni * 8;
            #pragma unroll
            for (int half = 0; half < 2; ++half) {
                const int row = rbase + mi * 16 + half * 8;
                float v0 = acc[mi][ni][half * 2 + 0];
                float v1 = acc[mi][ni][half * 2 + 1];
                if (EPI == 0) {
                    *(float2*)(C + (size_t)row * N + col) = {v0, v1};
                } else if (EPI == 1) {
                    const float2 rv = *(const float2*)(R + (size_t)row * N + col);
                    v0 += bias[col]     + rv.x;
                    v1 += bias[col + 1] + rv.y;
                    *(float2*)(C + (size_t)row * N + col) = {v0, v1};
                } else {
                    const float t0 = v0 + bias[col];
                    const float t1 = v1 + bias[col + 1];
                    const float g0 = 0.5f * t0 * (1.0f + erff(t0 * 0.70710678118654752f));
                    const float g1 = 0.5f * t1 * (1.0f + erff(t1 * 0.70710678118654752f));
                    *reinterpret_cast<__half2*>(Ch + (size_t)row * N + col) =
                        __floats2half2_rn(g0, g1);
                }
            }
        }
    }
}

// ======================= banded attention (shfl-free scores) =======================
// grid (T/64, H, B), block 256 (8 warps, 8 queries each).
#define AT_NK   192
#define KS_PAD  65
#define VS_PAD  66
#define KS_OFF  0
#define VS_OFF  (AT_NK * KS_PAD * 4)                    // 49920
#define QS_OFF  (VS_OFF + AT_NK * VS_PAD * 4)           // 100608
#define SC_OFF  (QS_OFF + 64 * 64 * 4)                  // 116992
#define ATT_DSMEM (SC_OFF + 8 * 136 * 4)                // 121344

__global__ __launch_bounds__(256, 1)
void attn_kernel(const float* __restrict__ qkv,
                 __half* __restrict__ ctx,
                 const int* __restrict__ csp, int T) {
    extern __shared__ char dsm[];
    float* Ks  = (float*)(dsm + KS_OFF);
    float* Vs  = (float*)(dsm + VS_OFF);
    float* Qs  = (float*)(dsm + QS_OFF);
    float* scb = (float*)(dsm + SC_OFF);

    const int cs = min(*csp, 64);
    const int tid = threadIdx.x;
    const int wid = tid >> 5;
    const int lane = tid & 31;
    const int q0 = blockIdx.x * 64;
    const int h = blockIdx.y;
    const int b = blockIdx.z;

    const int jlo = max(q0 - cs, 0);
    const int jhi = min(q0 + 63 + cs, T - 1);
    const int nk = jhi - jlo + 1;

    for (int i = tid; i < nk * 16; i += 256) {
        const int row = i >> 4, c = i & 15;
        const float4* src = (const float4*)(qkv + (size_t)(b * T + jlo + row) * (3 * DIM) + h * HDIM);
        const float4 kv = src[c + 128];
        const float4 vv = src[c + 256];
        float* kr = Ks + row * KS_PAD + c * 4;
        kr[0] = kv.x; kr[1] = kv.y; kr[2] = kv.z; kr[3] = kv.w;
        float* vr = Vs + row * VS_PAD + c * 4;
        *(float2*)(vr)     = {vv.x, vv.y};
        *(float2*)(vr + 2) = {vv.z, vv.w};
    }
    for (int i = tid; i < 64 * 16; i += 256) {
        const int row = i >> 4, c = i & 15;
        const float4* src = (const float4*)(qkv + (size_t)(b * T + q0 + row) * (3 * DIM) + h * HDIM);
        *(float4*)(Qs + row * 64 + c * 4) = src[c];
    }
    __syncthreads();

    float* sc = scb + wid * 136;
    const float scale = 0.125f;

    for (int qi = 0; qi < 8; ++qi) {
        const int qloc = wid * 8 + qi;
        const int t = q0 + qloc;
        const float* qrow = Qs + qloc * 64;
        const int jloq = max(t - cs, 0);
        const int jhiq = min(t + cs, T - 1);
        const int base = jloq - jlo;
        const int n = jhiq - jloq + 1;

        float s[5] = {0.0f, 0.0f, 0.0f, 0.0f, 0.0f};
        const float* kr[5];
        #pragma unroll
        for (int c = 0; c < 5; ++c) {
            const int j = c * 32 + lane;
            kr[c] = Ks + (size_t)min(base + j, AT_NK - 1) * KS_PAD;
        }
        #pragma unroll 8
        for (int d = 0; d < 64; ++d) {
            const float qd = qrow[d];
            #pragma unroll
            for (int c = 0; c < 5; ++c)
                s[c] = fmaf(qd, kr[c][d], s[c]);
        }
        float mx = -INFINITY;
        #pragma unroll
        for (int c = 0; c < 5; ++c) {
            const int j = c * 32 + lane;
            if (j < n) {
                s[c] *= scale;
                sc[j] = s[c];
                mx = fmaxf(mx, s[c]);
            }
        }
        #pragma unroll
        for (int off = 16; off > 0; off >>= 1)
            mx = fmaxf(mx, __shfl_xor_sync(0xFFFFFFFFu, mx, off));
        __syncwarp();

        float sum = 0.0f;
        for (int i = lane; i < n; i += 32) {
            const float p = __expf(sc[i] - mx);
            sc[i] = p;
            sum += p;
        }
        #pragma unroll
        for (int off = 16; off > 0; off >>= 1)
            sum += __shfl_xor_sync(0xFFFFFFFFu, sum, off);
        const float inv = 1.0f / sum;
        __syncwarp();

        float2 acc = {0.0f, 0.0f};
        for (int j = 0; j < n; ++j) {
            const float p = sc[j];
            const float2 vv = *(const float2*)(Vs + (size_t)(base + j) * VS_PAD + 2 * lane);
            acc.x = fmaf(p, vv.x, acc.x);
            acc.y = fmaf(p, vv.y, acc.y);
        }
        *reinterpret_cast<__half2*>(ctx + (size_t)(b * T + t) * DIM + h * HDIM + 2 * lane) =
            __floats2half2_rn(acc.x * inv, acc.y * inv);
        __syncwarp();
    }
}

// ======================= launcher =======================
extern "C" void kernel_launch(void* const* d_in, const int* in_sizes, int n_in,
                              void* d_out, int out_size) {
    const float* x       = (const float*)d_in[0];
    const float* norm1_w = (const float*)d_in[1];
    const float* norm2_w = (const float*)d_in[2];
    const float* w_qkv   = (const float*)d_in[3];
    const float* w_out   = (const float*)d_in[4];
    const float* b_out   = (const float*)d_in[5];
    const float* w1      = (const float*)d_in[6];
    const float* b1      = (const float*)d_in[7];
    const float* w2      = (const float*)d_in[8];
    const float* b2      = (const float*)d_in[9];
    const int*   cs      = (const int*)d_in[10];
    float*       out     = (float*)d_out;

    const int BT = in_sizes[0] / DIM;   // 8192
    const int T  = T_SEQ;
    const int B  = BT / T;

    __half *wqkvT, *woutT, *w1T, *w2T, *xn, *ctx, *hh;
    float *qkv, *x1;
    cudaGetSymbolAddress((void**)&wqkvT, g_wqkvT);
    cudaGetSymbolAddress((void**)&woutT, g_woutT);
    cudaGetSymbolAddress((void**)&w1T,   g_w1T);
    cudaGetSymbolAddress((void**)&w2T,   g_w2T);
    cudaGetSymbolAddress((void**)&xn,    g_xn);
    cudaGetSymbolAddress((void**)&ctx,   g_ctx);
    cudaGetSymbolAddress((void**)&hh,    g_hh);
    cudaGetSymbolAddress((void**)&qkv,   g_qkv);
    cudaGetSymbolAddress((void**)&x1,    g_x1);

    cudaFuncSetAttribute(gemm_mma<0>, cudaFuncAttributeMaxDynamicSharedMemorySize, GEMM_DSMEM);
    cudaFuncSetAttribute(gemm_mma<1>, cudaFuncAttributeMaxDynamicSharedMemorySize, GEMM_DSMEM);
    cudaFuncSetAttribute(gemm_mma<2>, cudaFuncAttributeMaxDynamicSharedMemorySize, GEMM_DSMEM);
    cudaFuncSetAttribute(attn_kernel, cudaFuncAttributeMaxDynamicSharedMemorySize, ATT_DSMEM);

    const dim3 wb(32, 8);
    wprep_kernel<<<dim3((3 * DIM) / 32, DIM / 32), wb>>>(w_qkv, wqkvT, DIM, 3 * DIM);
    wprep_kernel<<<dim3(DIM / 32, DIM / 32), wb>>>(w_out, woutT, DIM, DIM);
    wprep_kernel<<<dim3(FFN_DIM / 32, DIM / 32), wb>>>(w1, w1T, DIM, FFN_DIM);
    wprep_kernel<<<dim3(DIM / 32, FFN_DIM / 32), wb>>>(w2, w2T, FFN_DIM, DIM);

    // 1. xn = rmsnorm(x, norm1_w) -> f16
    rmsnorm_h_kernel<<<BT, 128>>>(x, norm1_w, xn);
    // 2. qkv = xn @ w_qkv (fp32 out)
    gemm_mma<0><<<dim3((3 * DIM) / 128, BT / 128), 256, GEMM_DSMEM>>>(
        xn, wqkvT, nullptr, nullptr, qkv, nullptr, BT, 3 * DIM, DIM);
    // 3. banded attention -> ctx f16
    attn_kernel<<<dim3(T / 64, NHEAD, B), 256, ATT_DSMEM>>>(qkv, ctx, cs, T);
    // 4. x1 = x + ctx @ w_out + b_out
    gemm_mma<1><<<dim3(DIM / 128, BT / 128), 256, GEMM_DSMEM>>>(
        ctx, woutT, b_out, x, x1, nullptr, BT, DIM, DIM);
    // 5. xn = rmsnorm(x1, norm2_w) -> f16
    rmsnorm_h_kernel<<<BT, 128>>>(x1, norm2_w, xn);
    // 6. h = gelu(xn @ w1 + b1) -> f16
    gemm_mma<2><<<dim3(FFN_DIM / 128, BT / 128), 256, GEMM_DSMEM>>>(
        xn, w1T, b1, nullptr, nullptr, hh, BT, FFN_DIM, DIM);
    // 7. out = x1 + h @ w2 + b2
    gemm_mma<1><<<dim3(DIM / 128, BT / 128), 256, GEMM_DSMEM>>>(
        hh, w2T, b2, x1, out, nullptr, BT, DIM, FFN_DIM);
}

// round 12
// speedup vs baseline: 4.2893x; 1.0244x over previous
#include <cuda_runtime.h>
#include <cuda_fp16.h>
#include <math.h>
#include <stdint.h>

// Problem shape (fixed by the dataset): B=4, T=2048, D=512, H=8, Hd=64, FFN=2048
#define T_SEQ   2048
#define DIM     512
#define NHEAD   8
#define HDIM    64
#define FFN_DIM 2048
#define MAX_BT  8192

// ======================= helpers =======================
__device__ __forceinline__ uint32_t smem_u32(const void* p) {
    uint32_t a;
    asm("{ .reg .u64 t; cvta.to.shared.u64 t, %1; cvt.u32.u64 %0, t; }" : "=r"(a) : "l"(p));
    return a;
}
__device__ __forceinline__ void cp16(uint32_t s, const void* g) {
    asm volatile("cp.async.ca.shared.global [%0], [%1], 16;" :: "r"(s), "l"(g));
}
#define CP_COMMIT() asm volatile("cp.async.commit_group;" ::: "memory")
#define CP_WAIT1()  asm volatile("cp.async.wait_group 1;" ::: "memory")

__device__ __forceinline__ void ldsm4(uint32_t* r, uint32_t addr) {
    asm volatile("ldmatrix.sync.aligned.m8n8.x4.shared.b16 {%0,%1,%2,%3}, [%4];"
        : "=r"(r[0]), "=r"(r[1]), "=r"(r[2]), "=r"(r[3]) : "r"(addr));
}
// f16 inputs, f32 accumulate
__device__ __forceinline__ void mma_f32(float* c, const uint32_t* a, const uint32_t* b) {
    asm volatile(
        "mma.sync.aligned.m16n8k16.row.col.f32.f16.f16.f32 "
        "{%0,%1,%2,%3}, {%4,%5,%6,%7}, {%8,%9}, {%0,%1,%2,%3};"
        : "+f"(c[0]), "+f"(c[1]), "+f"(c[2]), "+f"(c[3])
        : "r"(a[0]), "r"(a[1]), "r"(a[2]), "r"(a[3]), "r"(b[0]), "r"(b[1]));
}

// ======================= scratch =======================
__device__ __half g_wqkvT[3 * DIM * DIM];
__device__ __half g_woutT[DIM * DIM];
__device__ __half g_w1T[FFN_DIM * DIM];
__device__ __half g_w2T[DIM * FFN_DIM];
__device__ __half g_xn[MAX_BT * DIM];
__device__ __half g_ctx[MAX_BT * DIM];
__device__ __half g_hh[MAX_BT * FFN_DIM];
__device__ __half g_qkvh[MAX_BT * 3 * DIM];
__device__ float g_x1[MAX_BT * DIM];

// ======================= fused weight prep: all 4 weights, one launch ============
// seg0 wqkv(512,1536) 768 blk | seg1 wout(512,512) 256 | seg2 w1(512,2048) 1024 | seg3 w2(2048,512) 1024
__global__ void wprep_all(const float* __restrict__ W0, __half* __restrict__ T0,
                          const float* __restrict__ W1, __half* __restrict__ T1,
                          const float* __restrict__ W2, __half* __restrict__ T2,
                          const float* __restrict__ W3, __half* __restrict__ T3) {
    __shared__ float t[32][33];
    const int gid = blockIdx.x;
    const float* W; __half* T; int K, N, lb, gx;
    if (gid < 768)        { W = W0; T = T0; K = 512;  N = 1536; lb = gid;        gx = 48; }
    else if (gid < 1024)  { W = W1; T = T1; K = 512;  N = 512;  lb = gid - 768;  gx = 16; }
    else if (gid < 2048)  { W = W2; T = T2; K = 512;  N = 2048; lb = gid - 1024; gx = 64; }
    else                  { W = W3; T = T3; K = 2048; N = 512;  lb = gid - 2048; gx = 16; }
    const int n0 = (lb % gx) * 32, k0 = (lb / gx) * 32;
    const int tx = threadIdx.x, ty = threadIdx.y;
    #pragma unroll
    for (int i = 0; i < 4; ++i)
        t[ty + i * 8][tx] = W[(size_t)(k0 + ty + i * 8) * N + n0 + tx];
    __syncthreads();
    #pragma unroll
    for (int i = 0; i < 4; ++i)
        T[(size_t)(n0 + ty + i * 8) * K + k0 + tx] = __float2half_rn(t[tx][ty + i * 8]);
}

// ======================= rmsnorm -> f16 =======================
__global__ void rmsnorm_h_kernel(const float* __restrict__ x,
                                 const float* __restrict__ w,
                                 __half* __restrict__ y) {
    const int row = blockIdx.x;
    const int tid = threadIdx.x;  // 128
    const float4 v = reinterpret_cast<const float4*>(x + (size_t)row * DIM)[tid];
    float ss = v.x * v.x + v.y * v.y + v.z * v.z + v.w * v.w;
    #pragma unroll
    for (int off = 16; off > 0; off >>= 1)
        ss += __shfl_xor_sync(0xFFFFFFFFu, ss, off);
    __shared__ float red[4];
    const int warp = tid >> 5, lane = tid & 31;
    if (lane == 0) red[warp] = ss;
    __syncthreads();
    const float r = rsqrtf((red[0] + red[1] + red[2] + red[3]) * (1.0f / DIM) + 1e-6f);
    const float4 wv = reinterpret_cast<const float4*>(w)[tid];
    const size_t e = (size_t)row * DIM + tid * 4;
    *reinterpret_cast<__half2*>(y + e) =
        __floats2half2_rn(v.x * r * wv.x, v.y * r * wv.y);
    *reinterpret_cast<__half2*>(y + e + 2) =
        __floats2half2_rn(v.z * r * wv.z, v.w * r * wv.w);
}

// ======================= mma.sync GEMM (plain f16, f32 acc) ==============
// C[M,N] = sum_k A[M,K]*B^T[N,K]. 128x128 tile, 8 warps (64x32), K-slab 64,
// 3-stage cp.async, 2 CTAs/SM, SINGLE __syncthreads per slab (loads issued
// into the buffer consumed last iteration, protected by this iteration's barrier).
// SMEM row stride 72 b16 units (144B).
// EPI: 1 +bias+resid fp32 C; 2 +bias, gelu -> f16 Ch; 3 plain -> f16 Ch
#define PADK   72
#define MATB   (128 * 144)           // 18432 B per matrix tile
#define STAGEB (2 * MATB)            // A, B = 36864
#define NSTAGE 3
#define GEMM_DSMEM (NSTAGE * STAGEB) // 110592

template <int EPI>
__global__ __launch_bounds__(256, 2)
void gemm_mma(const __half* __restrict__ A, const __half* __restrict__ Bw,
              const float* __restrict__ bias, const float* __restrict__ R,
              float* __restrict__ C, __half* __restrict__ Ch,
              int M, int N, int K) {
    extern __shared__ char dsm[];
    const uint32_t sm0 = smem_u32(dsm);
    const int tid = threadIdx.x;
    const int wid = tid >> 5;
    const int lane = tid & 31;
    const int wm = wid & 1;
    const int wn = wid >> 1;
    const int bm = blockIdx.y * 128;
    const int bn = blockIdx.x * 128;

    const int NS = K / 64;

    auto load_slab = [&](int s, int buf) {
        const uint32_t st = sm0 + (uint32_t)buf * STAGEB;
        const int k0 = s * 64;
        #pragma unroll
        for (int i = 0; i < 4; ++i) {
            const int idx = tid + i * 256;        // 0..1023
            const int row = idx >> 3;             // 0..127
            const int c   = idx & 7;              // 0..7
            const uint32_t so = (uint32_t)(row * 144 + c * 16);
            cp16(st + 0 * MATB + so, A  + (size_t)(bm + row) * K + k0 + c * 8);
            cp16(st + 1 * MATB + so, Bw + (size_t)(bn + row) * K + k0 + c * 8);
        }
    };

    float acc[4][4][4] = {};

    load_slab(0, 0); CP_COMMIT();
    if (NS > 1) load_slab(1, 1);
    CP_COMMIT();

    const uint32_t aRow = (uint32_t)(wm * 64 + (lane & 15));
    const uint32_t aKo  = (uint32_t)((lane >> 4) * 8);
    const uint32_t bRow = (uint32_t)(wn * 32 + (lane & 7) + ((lane >> 4) << 3));
    const uint32_t bKo  = (uint32_t)(((lane >> 3) & 1) * 8);

    int cbuf = 0, lbuf = 2;
    for (int s = 0; s < NS; ++s) {
        CP_WAIT1();
        __syncthreads();
        if (s + 2 < NS) load_slab(s + 2, lbuf);
        CP_COMMIT();
        const uint32_t st = sm0 + (uint32_t)cbuf * STAGEB;
        if (++lbuf == NSTAGE) lbuf = 0;
        if (++cbuf == NSTAGE) cbuf = 0;

        #pragma unroll
        for (int kk = 0; kk < 64; kk += 16) {
            uint32_t bf[2][4];
            #pragma unroll
            for (int g = 0; g < 2; ++g) {
                const uint32_t off = ((bRow + g * 16) * PADK + kk + bKo) * 2;
                ldsm4(bf[g], st + 1 * MATB + off);
            }
            #pragma unroll
            for (int mi = 0; mi < 4; ++mi) {
                uint32_t ah[4];
                const uint32_t off = ((aRow + mi * 16) * PADK + kk + aKo) * 2;
                ldsm4(ah, st + 0 * MATB + off);
                #pragma unroll
                for (int ni = 0; ni < 4; ++ni) {
                    const int g = ni >> 1, sub = (ni & 1) * 2;
                    mma_f32(acc[mi][ni], ah, &bf[g][sub]);
                }
            }
        }
    }

    // epilogue
    const int cbase = bn + wn * 32 + (lane & 3) * 2;
    const int rbase = bm + wm * 64 + (lane >> 2);
    #pragma unroll
    for (int mi = 0; mi < 4; ++mi) {
        #pragma unroll
        for (int ni = 0; ni < 4; ++ni) {
            const int col = cbase + ni * 8;
            #pragma unroll
            for (int half = 0; half < 2; ++half) {
                const int row = rbase + mi * 16 + half * 8;
                float v0 = acc[mi][ni][half * 2 + 0];
                float v1 = acc[mi][ni][half * 2 + 1];
                if (EPI == 1) {
                    const float2 rv = *(const float2*)(R + (size_t)row * N + col);
                    v0 += bias[col]     + rv.x;
                    v1 += bias[col + 1] + rv.y;
                    *(float2*)(C + (size_t)row * N + col) = {v0, v1};
                } else if (EPI == 2) {
                    const float t0 = v0 + bias[col];
                    const float t1 = v1 + bias[col + 1];
                    const float g0 = 0.5f * t0 * (1.0f + erff(t0 * 0.70710678118654752f));
                    const float g1 = 0.5f * t1 * (1.0f + erff(t1 * 0.70710678118654752f));
                    *reinterpret_cast<__half2*>(Ch + (size_t)row * N + col) =
                        __floats2half2_rn(g0, g1);
                } else {
                    *reinterpret_cast<__half2*>(Ch + (size_t)row * N + col) =
                        __floats2half2_rn(v0, v1);
                }
            }
        }
    }
}

// ======================= banded attention (f16 qkv in, shfl-free scores) ==========
// grid (T/64, H, B), block 256 (8 warps, 8 queries each).
#define AT_NK   192
#define KS_PAD  65
#define VS_PAD  66
#define KS_OFF  0
#define VS_OFF  (AT_NK * KS_PAD * 4)                    // 49920
#define QS_OFF  (VS_OFF + AT_NK * VS_PAD * 4)           // 100608
#define SC_OFF  (QS_OFF + 64 * 64 * 4)                  // 116992
#define ATT_DSMEM (SC_OFF + 8 * 136 * 4)                // 121344

__global__ __launch_bounds__(256, 1)
void attn_kernel(const __half* __restrict__ qkv,
                 __half* __restrict__ ctx,
                 const int* __restrict__ csp, int T) {
    extern __shared__ char dsm[];
    float* Ks  = (float*)(dsm + KS_OFF);
    float* Vs  = (float*)(dsm + VS_OFF);
    float* Qs  = (float*)(dsm + QS_OFF);
    float* scb = (float*)(dsm + SC_OFF);

    const int cs = min(*csp, 64);
    const int tid = threadIdx.x;
    const int wid = tid >> 5;
    const int lane = tid & 31;
    const int q0 = blockIdx.x * 64;
    const int h = blockIdx.y;
    const int b = blockIdx.z;

    const int jlo = max(q0 - cs, 0);
    const int jhi = min(q0 + 63 + cs, T - 1);
    const int nk = jhi - jlo + 1;

    // load K/V band (f16 -> f32 smem); 8 x 16-half chunks per 64-wide row
    for (int i = tid; i < nk * 8; i += 256) {
        const int row = i >> 3, c = i & 7;
        const __half2* src = (const __half2*)(qkv + (size_t)(b * T + jlo + row) * (3 * DIM) + h * HDIM + c * 8);
        float* kr = Ks + row * KS_PAD + c * 8;
        float* vr = Vs + row * VS_PAD + c * 8;
        #pragma unroll
        for (int u = 0; u < 4; ++u) {
            const float2 kf = __half22float2(src[u + DIM / 2]);       // K at +DIM halfs
            const float2 vf = __half22float2(src[u + DIM]);           // V at +2*DIM halfs
            kr[u * 2]     = kf.x; kr[u * 2 + 1] = kf.y;
            vr[u * 2]     = vf.x; vr[u * 2 + 1] = vf.y;
        }
    }
    for (int i = tid; i < 64 * 8; i += 256) {
        const int row = i >> 3, c = i & 7;
        const __half2* src = (const __half2*)(qkv + (size_t)(b * T + q0 + row) * (3 * DIM) + h * HDIM + c * 8);
        float* qr = Qs + row * 64 + c * 8;
        #pragma unroll
        for (int u = 0; u < 4; ++u) {
            const float2 qf = __half22float2(src[u]);
            qr[u * 2] = qf.x; qr[u * 2 + 1] = qf.y;
        }
    }
    __syncthreads();

    float* sc = scb + wid * 136;
    const float scale = 0.125f;

    for (int qi = 0; qi < 8; ++qi) {
        const int qloc = wid * 8 + qi;
        const int t = q0 + qloc;
        const float* qrow = Qs + qloc * 64;
        const int jloq = max(t - cs, 0);
        const int jhiq = min(t + cs, T - 1);
        const int base = jloq - jlo;
        const int n = jhiq - jloq + 1;

        float s[5] = {0.0f, 0.0f, 0.0f, 0.0f, 0.0f};
        const float* kr[5];
        #pragma unroll
        for (int c = 0; c < 5; ++c) {
            const int j = c * 32 + lane;
            kr[c] = Ks + (size_t)min(base + j, AT_NK - 1) * KS_PAD;
        }
        #pragma unroll 8
        for (int d = 0; d < 64; ++d) {
            const float qd = qrow[d];
            #pragma unroll
            for (int c = 0; c < 5; ++c)
                s[c] = fmaf(qd, kr[c][d], s[c]);
        }
        float mx = -INFINITY;
        #pragma unroll
        for (int c = 0; c < 5; ++c) {
            const int j = c * 32 + lane;
            if (j < n) {
                s[c] *= scale;
                sc[j] = s[c];
                mx = fmaxf(mx, s[c]);
            }
        }
        #pragma unroll
        for (int off = 16; off > 0; off >>= 1)
            mx = fmaxf(mx, __shfl_xor_sync(0xFFFFFFFFu, mx, off));
        __syncwarp();

        float sum = 0.0f;
        for (int i = lane; i < n; i += 32) {
            const float p = __expf(sc[i] - mx);
            sc[i] = p;
            sum += p;
        }
        #pragma unroll
        for (int off = 16; off > 0; off >>= 1)
            sum += __shfl_xor_sync(0xFFFFFFFFu, sum, off);
        const float inv = 1.0f / sum;
        __syncwarp();

        // pass 3: two independent FMA chains to hide latency
        float2 a0 = {0.0f, 0.0f}, a1 = {0.0f, 0.0f};
        int j = 0;
        for (; j + 1 < n; j += 2) {
            const float p0 = sc[j], p1 = sc[j + 1];
            const float2 v0 = *(const float2*)(Vs + (size_t)(base + j) * VS_PAD + 2 * lane);
            const float2 v1 = *(const float2*)(Vs + (size_t)(base + j + 1) * VS_PAD + 2 * lane);
            a0.x = fmaf(p0, v0.x, a0.x);
            a0.y = fmaf(p0, v0.y, a0.y);
            a1.x = fmaf(p1, v1.x, a1.x);
            a1.y = fmaf(p1, v1.y, a1.y);
        }
        if (j < n) {
            const float p0 = sc[j];
            const float2 v0 = *(const float2*)(Vs + (size_t)(base + j) * VS_PAD + 2 * lane);
            a0.x = fmaf(p0, v0.x, a0.x);
            a0.y = fmaf(p0, v0.y, a0.y);
        }
        *reinterpret_cast<__half2*>(ctx + (size_t)(b * T + t) * DIM + h * HDIM + 2 * lane) =
            __floats2half2_rn((a0.x + a1.x) * inv, (a0.y + a1.y) * inv);
        __syncwarp();
    }
}

// ======================= launcher =======================
extern "C" void kernel_launch(void* const* d_in, const int* in_sizes, int n_in,
                              void* d_out, int out_size) {
    const float* x       = (const float*)d_in[0];
    const float* norm1_w = (const float*)d_in[1];
    const float* norm2_w = (const float*)d_in[2];
    const float* w_qkv   = (const float*)d_in[3];
    const float* w_out   = (const float*)d_in[4];
    const float* b_out   = (const float*)d_in[5];
    const float* w1      = (const float*)d_in[6];
    const float* b1      = (const float*)d_in[7];
    const float* w2      = (const float*)d_in[8];
    const float* b2      = (const float*)d_in[9];
    const int*   cs      = (const int*)d_in[10];
    float*       out     = (float*)d_out;

    const int BT = in_sizes[0] / DIM;   // 8192
    const int T  = T_SEQ;
    const int B  = BT / T;

    __half *wqkvT, *woutT, *w1T, *w2T, *xn, *ctx, *hh, *qkvh;
    float *x1;
    cudaGetSymbolAddress((void**)&wqkvT, g_wqkvT);
    cudaGetSymbolAddress((void**)&woutT, g_woutT);
    cudaGetSymbolAddress((void**)&w1T,   g_w1T);
    cudaGetSymbolAddress((void**)&w2T,   g_w2T);
    cudaGetSymbolAddress((void**)&xn,    g_xn);
    cudaGetSymbolAddress((void**)&ctx,   g_ctx);
    cudaGetSymbolAddress((void**)&hh,    g_hh);
    cudaGetSymbolAddress((void**)&qkvh,  g_qkvh);
    cudaGetSymbolAddress((void**)&x1,    g_x1);

    cudaFuncSetAttribute(gemm_mma<1>, cudaFuncAttributeMaxDynamicSharedMemorySize, GEMM_DSMEM);
    cudaFuncSetAttribute(gemm_mma<2>, cudaFuncAttributeMaxDynamicSharedMemorySize, GEMM_DSMEM);
    cudaFuncSetAttribute(gemm_mma<3>, cudaFuncAttributeMaxDynamicSharedMemorySize, GEMM_DSMEM);
    cudaFuncSetAttribute(attn_kernel, cudaFuncAttributeMaxDynamicSharedMemorySize, ATT_DSMEM);

    // 0. all weight preps in one launch
    wprep_all<<<3072, dim3(32, 8)>>>(w_qkv, wqkvT, w_out, woutT, w1, w1T, w2, w2T);

    // 1. xn = rmsnorm(x, norm1_w) -> f16
    rmsnorm_h_kernel<<<BT, 128>>>(x, norm1_w, xn);
    // 2. qkv = xn @ w_qkv -> f16
    gemm_mma<3><<<dim3((3 * DIM) / 128, BT / 128), 256, GEMM_DSMEM>>>(
        xn, wqkvT, nullptr, nullptr, nullptr, qkvh, BT, 3 * DIM, DIM);
    // 3. banded attention -> ctx f16
    attn_kernel<<<dim3(T / 64, NHEAD, B), 256, ATT_DSMEM>>>(qkvh, ctx, cs, T);
    // 4. x1 = x + ctx @ w_out + b_out (fp32)
    gemm_mma<1><<<dim3(DIM / 128, BT / 128), 256, GEMM_DSMEM>>>(
        ctx, woutT, b_out, x, x1, nullptr, BT, DIM, DIM);
    // 5. xn = rmsnorm(x1, norm2_w) -> f16
    rmsnorm_h_kernel<<<BT, 128>>>(x1, norm2_w, xn);
    // 6. h = gelu(xn @ w1 + b1) -> f16
    gemm_mma<2><<<dim3(FFN_DIM / 128, BT / 128), 256, GEMM_DSMEM>>>(
        xn, w1T, b1, nullptr, nullptr, hh, BT, FFN_DIM, DIM);
    // 7. out = x1 + h @ w2 + b2
    gemm_mma<1><<<dim3(DIM / 128, BT / 128), 256, GEMM_DSMEM>>>(
        hh, w2T, b2, x1, out, nullptr, BT, DIM, FFN_DIM);
}

// round 14
// speedup vs baseline: 6.8430x; 1.5954x over previous
#include <cuda_runtime.h>
#include <cuda_fp16.h>
#include <math.h>
#include <stdint.h>

// Problem shape (fixed by the dataset): B=4, T=2048, D=512, H=8, Hd=64, FFN=2048
#define T_SEQ   2048
#define DIM     512
#define NHEAD   8
#define HDIM    64
#define FFN_DIM 2048
#define MAX_BT  8192

// ======================= helpers =======================
__device__ __forceinline__ uint32_t smem_u32(const void* p) {
    uint32_t a;
    asm("{ .reg .u64 t; cvta.to.shared.u64 t, %1; cvt.u32.u64 %0, t; }" : "=r"(a) : "l"(p));
    return a;
}
__device__ __forceinline__ void cp16(uint32_t s, const void* g) {
    asm volatile("cp.async.ca.shared.global [%0], [%1], 16;" :: "r"(s), "l"(g));
}
#define CP_COMMIT() asm volatile("cp.async.commit_group;" ::: "memory")
#define CP_WAIT1()  asm volatile("cp.async.wait_group 1;" ::: "memory")

__device__ __forceinline__ void ldsm4(uint32_t* r, uint32_t addr) {
    asm volatile("ldmatrix.sync.aligned.m8n8.x4.shared.b16 {%0,%1,%2,%3}, [%4];"
        : "=r"(r[0]), "=r"(r[1]), "=r"(r[2]), "=r"(r[3]) : "r"(addr));
}
// f16 inputs, f32 accumulate
__device__ __forceinline__ void mma_f32(float* c, const uint32_t* a, const uint32_t* b) {
    asm volatile(
        "mma.sync.aligned.m16n8k16.row.col.f32.f16.f16.f32 "
        "{%0,%1,%2,%3}, {%4,%5,%6,%7}, {%8,%9}, {%0,%1,%2,%3};"
        : "+f"(c[0]), "+f"(c[1]), "+f"(c[2]), "+f"(c[3])
        : "r"(a[0]), "r"(a[1]), "r"(a[2]), "r"(a[3]), "r"(b[0]), "r"(b[1]));
}

// ======================= scratch =======================
__device__ __half g_wqkvT[3 * DIM * DIM];
__device__ __half g_woutT[DIM * DIM];
__device__ __half g_w1T[FFN_DIM * DIM];
__device__ __half g_w2T[DIM * FFN_DIM];
__device__ __half g_xn[MAX_BT * DIM];
__device__ __half g_ctx[MAX_BT * DIM];
__device__ __half g_hh[MAX_BT * FFN_DIM];
__device__ __half g_qkvh[MAX_BT * 3 * DIM];
__device__ float g_x1[MAX_BT * DIM];

// ======================= fused weight prep: all 4 weights, one launch ============
__global__ void wprep_all(const float* __restrict__ W0, __half* __restrict__ T0,
                          const float* __restrict__ W1, __half* __restrict__ T1,
                          const float* __restrict__ W2, __half* __restrict__ T2,
                          const float* __restrict__ W3, __half* __restrict__ T3) {
    __shared__ float t[32][33];
    const int gid = blockIdx.x;
    const float* W; __half* T; int K, N, lb, gx;
    if (gid < 768)        { W = W0; T = T0; K = 512;  N = 1536; lb = gid;        gx = 48; }
    else if (gid < 1024)  { W = W1; T = T1; K = 512;  N = 512;  lb = gid - 768;  gx = 16; }
    else if (gid < 2048)  { W = W2; T = T2; K = 512;  N = 2048; lb = gid - 1024; gx = 64; }
    else                  { W = W3; T = T3; K = 2048; N = 512;  lb = gid - 2048; gx = 16; }
    const int n0 = (lb % gx) * 32, k0 = (lb / gx) * 32;
    const int tx = threadIdx.x, ty = threadIdx.y;
    #pragma unroll
    for (int i = 0; i < 4; ++i)
        t[ty + i * 8][tx] = W[(size_t)(k0 + ty + i * 8) * N + n0 + tx];
    __syncthreads();
    #pragma unroll
    for (int i = 0; i < 4; ++i)
        T[(size_t)(n0 + ty + i * 8) * K + k0 + tx] = __float2half_rn(t[tx][ty + i * 8]);
}

// ======================= rmsnorm -> f16 =======================
__global__ void rmsnorm_h_kernel(const float* __restrict__ x,
                                 const float* __restrict__ w,
                                 __half* __restrict__ y) {
    const int row = blockIdx.x;
    const int tid = threadIdx.x;  // 128
    const float4 v = reinterpret_cast<const float4*>(x + (size_t)row * DIM)[tid];
    float ss = v.x * v.x + v.y * v.y + v.z * v.z + v.w * v.w;
    #pragma unroll
    for (int off = 16; off > 0; off >>= 1)
        ss += __shfl_xor_sync(0xFFFFFFFFu, ss, off);
    __shared__ float red[4];
    const int warp = tid >> 5, lane = tid & 31;
    if (lane == 0) red[warp] = ss;
    __syncthreads();
    const float r = rsqrtf((red[0] + red[1] + red[2] + red[3]) * (1.0f / DIM) + 1e-6f);
    const float4 wv = reinterpret_cast<const float4*>(w)[tid];
    const size_t e = (size_t)row * DIM + tid * 4;
    *reinterpret_cast<__half2*>(y + e) =
        __floats2half2_rn(v.x * r * wv.x, v.y * r * wv.y);
    *reinterpret_cast<__half2*>(y + e + 2) =
        __floats2half2_rn(v.z * r * wv.z, v.w * r * wv.w);
}

// ======================= mma.sync GEMM (plain f16, f32 acc) ==============
// Unchanged from round 12 (passed). Single sync per slab, 3-stage, 2 CTAs/SM.
#define PADK   72
#define MATB   (128 * 144)
#define STAGEB (2 * MATB)
#define NSTAGE 3
#define GEMM_DSMEM (NSTAGE * STAGEB)

template <int EPI>
__global__ __launch_bounds__(256, 2)
void gemm_mma(const __half* __restrict__ A, const __half* __restrict__ Bw,
              const float* __restrict__ bias, const float* __restrict__ R,
              float* __restrict__ C, __half* __restrict__ Ch,
              int M, int N, int K) {
    extern __shared__ char dsm[];
    const uint32_t sm0 = smem_u32(dsm);
    const int tid = threadIdx.x;
    const int wid = tid >> 5;
    const int lane = tid & 31;
    const int wm = wid & 1;
    const int wn = wid >> 1;
    const int bm = blockIdx.y * 128;
    const int bn = blockIdx.x * 128;

    const int NS = K / 64;

    auto load_slab = [&](int s, int buf) {
        const uint32_t st = sm0 + (uint32_t)buf * STAGEB;
        const int k0 = s * 64;
        #pragma unroll
        for (int i = 0; i < 4; ++i) {
            const int idx = tid + i * 256;
            const int row = idx >> 3;
            const int c   = idx & 7;
            const uint32_t so = (uint32_t)(row * 144 + c * 16);
            cp16(st + 0 * MATB + so, A  + (size_t)(bm + row) * K + k0 + c * 8);
            cp16(st + 1 * MATB + so, Bw + (size_t)(bn + row) * K + k0 + c * 8);
        }
    };

    float acc[4][4][4] = {};

    load_slab(0, 0); CP_COMMIT();
    if (NS > 1) load_slab(1, 1);
    CP_COMMIT();

    const uint32_t aRow = (uint32_t)(wm * 64 + (lane & 15));
    const uint32_t aKo  = (uint32_t)((lane >> 4) * 8);
    const uint32_t bRow = (uint32_t)(wn * 32 + (lane & 7) + ((lane >> 4) << 3));
    const uint32_t bKo  = (uint32_t)(((lane >> 3) & 1) * 8);

    int cbuf = 0, lbuf = 2;
    for (int s = 0; s < NS; ++s) {
        CP_WAIT1();
        __syncthreads();
        if (s + 2 < NS) load_slab(s + 2, lbuf);
        CP_COMMIT();
        const uint32_t st = sm0 + (uint32_t)cbuf * STAGEB;
        if (++lbuf == NSTAGE) lbuf = 0;
        if (++cbuf == NSTAGE) cbuf = 0;

        #pragma unroll
        for (int kk = 0; kk < 64; kk += 16) {
            uint32_t bf[2][4];
            #pragma unroll
            for (int g = 0; g < 2; ++g) {
                const uint32_t off = ((bRow + g * 16) * PADK + kk + bKo) * 2;
                ldsm4(bf[g], st + 1 * MATB + off);
            }
            #pragma unroll
            for (int mi = 0; mi < 4; ++mi) {
                uint32_t ah[4];
                const uint32_t off = ((aRow + mi * 16) * PADK + kk + aKo) * 2;
                ldsm4(ah, st + 0 * MATB + off);
                #pragma unroll
                for (int ni = 0; ni < 4; ++ni) {
                    const int g = ni >> 1, sub = (ni & 1) * 2;
                    mma_f32(acc[mi][ni], ah, &bf[g][sub]);
                }
            }
        }
    }

    const int cbase = bn + wn * 32 + (lane & 3) * 2;
    const int rbase = bm + wm * 64 + (lane >> 2);
    #pragma unroll
    for (int mi = 0; mi < 4; ++mi) {
        #pragma unroll
        for (int ni = 0; ni < 4; ++ni) {
            const int col = cbase + ni * 8;
            #pragma unroll
            for (int half = 0; half < 2; ++half) {
                const int row = rbase + mi * 16 + half * 8;
                float v0 = acc[mi][ni][half * 2 + 0];
                float v1 = acc[mi][ni][half * 2 + 1];
                if (EPI == 1) {
                    const float2 rv = *(const float2*)(R + (size_t)row * N + col);
                    v0 += bias[col]     + rv.x;
                    v1 += bias[col + 1] + rv.y;
                    *(float2*)(C + (size_t)row * N + col) = {v0, v1};
                } else if (EPI == 2) {
                    const float t0 = v0 + bias[col];
                    const float t1 = v1 + bias[col + 1];
                    const float g0 = 0.5f * t0 * (1.0f + erff(t0 * 0.70710678118654752f));
                    const float g1 = 0.5f * t1 * (1.0f + erff(t1 * 0.70710678118654752f));
                    *reinterpret_cast<__half2*>(Ch + (size_t)row * N + col) =
                        __floats2half2_rn(g0, g1);
                } else {
                    *reinterpret_cast<__half2*>(Ch + (size_t)row * N + col) =
                        __floats2half2_rn(v0, v1);
                }
            }
        }
    }
}

// ======================= flash-style banded attention (tensor-core) ==============
// grid (T/128, H, B), block 256 = 8 warps; warp w owns query rows w*16..w*16+15.
// S = (Q*0.125) @ K^T over a per-warp 144-col key window; mask+softmax in
// fragments; P (f16, in-register C->A fragment identity) @ V^T (V transposed
// into smem, d-major) -> O.  Scale folded into Q (0.125 exact in f16).
#define AQ_OFF  0
#define AK_OFF  18432                      // Qs: 128 x 72 halves
#define AV_OFF  (18432 + 36864)            // Ks: 256 x 72 halves
#define VT_PAD  264                        // Vt: 64 x 264 halves = 33792 B
#define ATT_DSMEM (AV_OFF + 64 * VT_PAD * 2)   // 89088

__global__ __launch_bounds__(256)
void attn_kernel(const __half* __restrict__ qkv,
                 __half* __restrict__ ctx,
                 const int* __restrict__ csp, int T) {
    extern __shared__ char dsm[];
    __half* Qs = (__half*)(dsm + AQ_OFF);
    __half* Ks = (__half*)(dsm + AK_OFF);
    __half* Vt = (__half*)(dsm + AV_OFF);

    const int cs = min(*csp, 64);
    const int tid = threadIdx.x;
    const int wid = tid >> 5;
    const int lane = tid & 31;
    const int q0 = blockIdx.x * 128;
    const int h = blockIdx.y;
    const int b = blockIdx.z;

    const int jlo = max(q0 - cs, 0);
    const int jhi = min(q0 + 127 + cs, T - 1);
    const int nk = jhi - jlo + 1;

    const size_t gbase = (size_t)(b * T) * (3 * DIM) + h * HDIM;

    // ---- load Q (scaled by 0.125), K (zero-padded), V transposed ----
    const __half2 qsc = __float2half2_rn(0.125f);
    for (int i = tid; i < 128 * 8; i += 256) {
        const int row = i >> 3, c = i & 7;
        const __half2* src = (const __half2*)(qkv + gbase + (size_t)(q0 + row) * (3 * DIM) + c * 8);
        __half2* dst = (__half2*)(Qs + row * 72 + c * 8);
        #pragma unroll
        for (int u = 0; u < 4; ++u) dst[u] = __hmul2(src[u], qsc);
    }
    for (int i = tid; i < 256 * 8; i += 256) {
        const int row = i >> 3, c = i & 7;
        uint4 val = {0u, 0u, 0u, 0u};
        if (row < nk)
            val = *(const uint4*)(qkv + gbase + (size_t)(jlo + row) * (3 * DIM) + DIM + c * 8);
        *(uint4*)(Ks + row * 72 + c * 8) = val;
    }
    for (int i = tid; i < 8192; i += 256) {
        const int key = i & 255, dp = i >> 8;   // dp = d-pair index 0..31
        __half2 v = __floats2half2_rn(0.0f, 0.0f);
        if (key < nk)
            v = *(const __half2*)(qkv + gbase + (size_t)(jlo + key) * (3 * DIM) + 2 * DIM + dp * 2);
        Vt[(2 * dp)     * VT_PAD + key] = __low2half(v);
        Vt[(2 * dp + 1) * VT_PAD + key] = __high2half(v);
    }
    __syncthreads();

    const uint32_t sQ = smem_u32(Qs), sK = smem_u32(Ks), sV = smem_u32(Vt);

    // per-warp key window: 144 cols starting at nb (8-aligned)
    int nb = q0 + wid * 16 - cs - jlo;
    nb = (nb < 0 ? 0 : nb) & ~7;

    // Q A-fragments (m16 x k64 = 4 k16 chunks), loaded once
    const uint32_t aRow = (uint32_t)(wid * 16 + (lane & 15));
    const uint32_t aKo  = (uint32_t)((lane >> 4) * 8);
    uint32_t aq[4][4];
    #pragma unroll
    for (int kk = 0; kk < 4; ++kk)
        ldsm4(aq[kk], sQ + (aRow * 72 + kk * 16 + aKo) * 2);

    const uint32_t bR  = (uint32_t)((lane & 7) + ((lane >> 4) << 3));
    const uint32_t bKo = (uint32_t)(((lane >> 3) & 1) * 8);

    // ---- S = Q @ K^T : 18 n8 tiles ----
    float sacc[18][4] = {};
    #pragma unroll
    for (int ng = 0; ng < 9; ++ng) {
        #pragma unroll
        for (int kk = 0; kk < 4; ++kk) {
            uint32_t bf[4];
            ldsm4(bf, sK + ((uint32_t)(nb + ng * 16 + bR) * 72 + kk * 16 + bKo) * 2);
            mma_f32(sacc[ng * 2],     aq[kk], &bf[0]);
            mma_f32(sacc[ng * 2 + 1], aq[kk], &bf[2]);
        }
    }

    // ---- mask + softmax in fragments ----
    const int r0 = q0 + wid * 16 + (lane >> 2);   // global query row
    const int r1 = r0 + 8;
    const int cb = jlo + nb + 2 * (lane & 3);     // global key of col pair base
    float m0 = -INFINITY, m1 = -INFINITY;
    #pragma unroll
    for (int t = 0; t < 18; ++t) {
        const int k0 = cb + t * 8, k1 = k0 + 1;
        if (k0 < r0 - cs || k0 > r0 + cs || k0 > jhi) sacc[t][0] = -INFINITY;
        if (k1 < r0 - cs || k1 > r0 + cs || k1 > jhi) sacc[t][1] = -INFINITY;
        if (k0 < r1 - cs || k0 > r1 + cs || k0 > jhi) sacc[t][2] = -INFINITY;
        if (k1 < r1 - cs || k1 > r1 + cs || k1 > jhi) sacc[t][3] = -INFINITY;
        m0 = fmaxf(m0, fmaxf(sacc[t][0], sacc[t][1]));
        m1 = fmaxf(m1, fmaxf(sacc[t][2], sacc[t][3]));
    }
    m0 = fmaxf(m0, __shfl_xor_sync(0xFFFFFFFFu, m0, 1));
    m0 = fmaxf(m0, __shfl_xor_sync(0xFFFFFFFFu, m0, 2));
    m1 = fmaxf(m1, __shfl_xor_sync(0xFFFFFFFFu, m1, 1));
    m1 = fmaxf(m1, __shfl_xor_sync(0xFFFFFFFFu, m1, 2));

    float sum0 = 0.0f, sum1 = 0.0f;
    uint32_t pf[18][2];
    #pragma unroll
    for (int t = 0; t < 18; ++t) {
        const float p00 = __expf(sacc[t][0] - m0);
        const float p01 = __expf(sacc[t][1] - m0);
        const float p10 = __expf(sacc[t][2] - m1);
        const float p11 = __expf(sacc[t][3] - m1);
        sum0 += p00 + p01;
        sum1 += p10 + p11;
        const __half2 h0 = __floats2half2_rn(p00, p01);
        const __half2 h1 = __floats2half2_rn(p10, p11);
        pf[t][0] = *reinterpret_cast<const uint32_t*>(&h0);
        pf[t][1] = *reinterpret_cast<const uint32_t*>(&h1);
    }
    sum0 += __shfl_xor_sync(0xFFFFFFFFu, sum0, 1);
    sum0 += __shfl_xor_sync(0xFFFFFFFFu, sum0, 2);
    sum1 += __shfl_xor_sync(0xFFFFFFFFu, sum1, 1);
    sum1 += __shfl_xor_sync(0xFFFFFFFFu, sum1, 2);
    const float inv0 = 1.0f / sum0;
    const float inv1 = 1.0f / sum1;

    // ---- O = P @ V : P fragments reused in-register (C->A identity) ----
    float oacc[8][4] = {};
    #pragma unroll
    for (int j = 0; j < 9; ++j) {
        uint32_t pa[4] = {pf[2 * j][0], pf[2 * j][1], pf[2 * j + 1][0], pf[2 * j + 1][1]};
        #pragma unroll
        for (int ng = 0; ng < 4; ++ng) {
            uint32_t bf[4];
            ldsm4(bf, sV + ((uint32_t)(ng * 16 + bR) * VT_PAD + nb + j * 16 + bKo) * 2);
            mma_f32(oacc[ng * 2],     pa, &bf[0]);
            mma_f32(oacc[ng * 2 + 1], pa, &bf[2]);
        }
    }

    // ---- epilogue: normalize + store f16 ctx ----
    const size_t e0 = (size_t)(b * T + r0) * DIM + h * HDIM;
    const size_t e1 = (size_t)(b * T + r1) * DIM + h * HDIM;
    #pragma unroll
    for (int ni = 0; ni < 8; ++ni) {
        const int d = ni * 8 + 2 * (lane & 3);
        *reinterpret_cast<__half2*>(ctx + e0 + d) =
            __floats2half2_rn(oacc[ni][0] * inv0, oacc[ni][1] * inv0);
        *reinterpret_cast<__half2*>(ctx + e1 + d) =
            __floats2half2_rn(oacc[ni][2] * inv1, oacc[ni][3] * inv1);
    }
}

// ======================= launcher =======================
extern "C" void kernel_launch(void* const* d_in, const int* in_sizes, int n_in,
                              void* d_out, int out_size) {
    const float* x       = (const float*)d_in[0];
    const float* norm1_w = (const float*)d_in[1];
    const float* norm2_w = (const float*)d_in[2];
    const float* w_qkv   = (const float*)d_in[3];
    const float* w_out   = (const float*)d_in[4];
    const float* b_out   = (const float*)d_in[5];
    const float* w1      = (const float*)d_in[6];
    const float* b1      = (const float*)d_in[7];
    const float* w2      = (const float*)d_in[8];
    const float* b2      = (const float*)d_in[9];
    const int*   cs      = (const int*)d_in[10];
    float*       out     = (float*)d_out;

    const int BT = in_sizes[0] / DIM;   // 8192
    const int T  = T_SEQ;
    const int B  = BT / T;

    __half *wqkvT, *woutT, *w1T, *w2T, *xn, *ctx, *hh, *qkvh;
    float *x1;
    cudaGetSymbolAddress((void**)&wqkvT, g_wqkvT);
    cudaGetSymbolAddress((void**)&woutT, g_woutT);
    cudaGetSymbolAddress((void**)&w1T,   g_w1T);
    cudaGetSymbolAddress((void**)&w2T,   g_w2T);
    cudaGetSymbolAddress((void**)&xn,    g_xn);
    cudaGetSymbolAddress((void**)&ctx,   g_ctx);
    cudaGetSymbolAddress((void**)&hh,    g_hh);
    cudaGetSymbolAddress((void**)&qkvh,  g_qkvh);
    cudaGetSymbolAddress((void**)&x1,    g_x1);

    cudaFuncSetAttribute(gemm_mma<1>, cudaFuncAttributeMaxDynamicSharedMemorySize, GEMM_DSMEM);
    cudaFuncSetAttribute(gemm_mma<2>, cudaFuncAttributeMaxDynamicSharedMemorySize, GEMM_DSMEM);
    cudaFuncSetAttribute(gemm_mma<3>, cudaFuncAttributeMaxDynamicSharedMemorySize, GEMM_DSMEM);
    cudaFuncSetAttribute(attn_kernel, cudaFuncAttributeMaxDynamicSharedMemorySize, ATT_DSMEM);

    // 0. all weight preps in one launch
    wprep_all<<<3072, dim3(32, 8)>>>(w_qkv, wqkvT, w_out, woutT, w1, w1T, w2, w2T);

    // 1. xn = rmsnorm(x, norm1_w) -> f16
    rmsnorm_h_kernel<<<BT, 128>>>(x, norm1_w, xn);
    // 2. qkv = xn @ w_qkv -> f16
    gemm_mma<3><<<dim3((3 * DIM) / 128, BT / 128), 256, GEMM_DSMEM>>>(
        xn, wqkvT, nullptr, nullptr, nullptr, qkvh, BT, 3 * DIM, DIM);
    // 3. banded attention (tensor-core) -> ctx f16
    attn_kernel<<<dim3(T / 128, NHEAD, B), 256, ATT_DSMEM>>>(qkvh, ctx, cs, T);
    // 4. x1 = x + ctx @ w_out + b_out (fp32)
    gemm_mma<1><<<dim3(DIM / 128, BT / 128), 256, GEMM_DSMEM>>>(
        ctx, woutT, b_out, x, x1, nullptr, BT, DIM, DIM);
    // 5. xn = rmsnorm(x1, norm2_w) -> f16
    rmsnorm_h_kernel<<<BT, 128>>>(x1, norm2_w, xn);
    // 6. h = gelu(xn @ w1 + b1) -> f16
    gemm_mma<2><<<dim3(FFN_DIM / 128, BT / 128), 256, GEMM_DSMEM>>>(
        xn, w1T, b1, nullptr, nullptr, hh, BT, FFN_DIM, DIM);
    // 7. out = x1 + h @ w2 + b2
    gemm_mma<1><<<dim3(DIM / 128, BT / 128), 256, GEMM_DSMEM>>>(
        hh, w2T, b2, x1, out, nullptr, BT, DIM, FFN_DIM);
}

// round 15
// speedup vs baseline: 6.8510x; 1.0012x over previous
#include <cuda_runtime.h>
#include <cuda_fp16.h>
#include <math.h>
#include <stdint.h>

// Problem shape (fixed by the dataset): B=4, T=2048, D=512, H=8, Hd=64, FFN=2048
#define T_SEQ   2048
#define DIM     512
#define NHEAD   8
#define HDIM    64
#define FFN_DIM 2048
#define MAX_BT  8192

// ======================= helpers =======================
__device__ __forceinline__ uint32_t smem_u32(const void* p) {
    uint32_t a;
    asm("{ .reg .u64 t; cvta.to.shared.u64 t, %1; cvt.u32.u64 %0, t; }" : "=r"(a) : "l"(p));
    return a;
}
__device__ __forceinline__ void cp16(uint32_t s, const void* g) {
    asm volatile("cp.async.ca.shared.global [%0], [%1], 16;" :: "r"(s), "l"(g));
}
#define CP_COMMIT() asm volatile("cp.async.commit_group;" ::: "memory")
#define CP_WAIT1()  asm volatile("cp.async.wait_group 1;" ::: "memory")

__device__ __forceinline__ void ldsm4(uint32_t* r, uint32_t addr) {
    asm volatile("ldmatrix.sync.aligned.m8n8.x4.shared.b16 {%0,%1,%2,%3}, [%4];"
        : "=r"(r[0]), "=r"(r[1]), "=r"(r[2]), "=r"(r[3]) : "r"(addr));
}
// f16 inputs, f32 accumulate
__device__ __forceinline__ void mma_f32(float* c, const uint32_t* a, const uint32_t* b) {
    asm volatile(
        "mma.sync.aligned.m16n8k16.row.col.f32.f16.f16.f32 "
        "{%0,%1,%2,%3}, {%4,%5,%6,%7}, {%8,%9}, {%0,%1,%2,%3};"
        : "+f"(c[0]), "+f"(c[1]), "+f"(c[2]), "+f"(c[3])
        : "r"(a[0]), "r"(a[1]), "r"(a[2]), "r"(a[3]), "r"(b[0]), "r"(b[1]));
}

// ======================= scratch =======================
__device__ __half g_wqkvT[3 * DIM * DIM];
__device__ __half g_woutT[DIM * DIM];
__device__ __half g_w1T[FFN_DIM * DIM];
__device__ __half g_w2T[DIM * FFN_DIM];
__device__ __half g_xn[MAX_BT * DIM];
__device__ __half g_ctx[MAX_BT * DIM];
__device__ __half g_hh[MAX_BT * FFN_DIM];
__device__ __half g_qkvh[MAX_BT * 3 * DIM];
__device__ float g_x1[MAX_BT * DIM];

// ======================= fused weight prep: all 4 weights, one launch ============
__global__ void wprep_all(const float* __restrict__ W0, __half* __restrict__ T0,
                          const float* __restrict__ W1, __half* __restrict__ T1,
                          const float* __restrict__ W2, __half* __restrict__ T2,
                          const float* __restrict__ W3, __half* __restrict__ T3) {
    __shared__ float t[32][33];
    const int gid = blockIdx.x;
    const float* W; __half* T; int K, N, lb, gx;
    if (gid < 768)        { W = W0; T = T0; K = 512;  N = 1536; lb = gid;        gx = 48; }
    else if (gid < 1024)  { W = W1; T = T1; K = 512;  N = 512;  lb = gid - 768;  gx = 16; }
    else if (gid < 2048)  { W = W2; T = T2; K = 512;  N = 2048; lb = gid - 1024; gx = 64; }
    else                  { W = W3; T = T3; K = 2048; N = 512;  lb = gid - 2048; gx = 16; }
    const int n0 = (lb % gx) * 32, k0 = (lb / gx) * 32;
    const int tx = threadIdx.x, ty = threadIdx.y;
    #pragma unroll
    for (int i = 0; i < 4; ++i)
        t[ty + i * 8][tx] = W[(size_t)(k0 + ty + i * 8) * N + n0 + tx];
    __syncthreads();
    #pragma unroll
    for (int i = 0; i < 4; ++i)
        T[(size_t)(n0 + ty + i * 8) * K + k0 + tx] = __float2half_rn(t[tx][ty + i * 8]);
}

// ======================= rmsnorm -> f16 =======================
__global__ void rmsnorm_h_kernel(const float* __restrict__ x,
                                 const float* __restrict__ w,
                                 __half* __restrict__ y) {
    const int row = blockIdx.x;
    const int tid = threadIdx.x;  // 128
    const float4 v = reinterpret_cast<const float4*>(x + (size_t)row * DIM)[tid];
    float ss = v.x * v.x + v.y * v.y + v.z * v.z + v.w * v.w;
    #pragma unroll
    for (int off = 16; off > 0; off >>= 1)
        ss += __shfl_xor_sync(0xFFFFFFFFu, ss, off);
    __shared__ float red[4];
    const int warp = tid >> 5, lane = tid & 31;
    if (lane == 0) red[warp] = ss;
    __syncthreads();
    const float r = rsqrtf((red[0] + red[1] + red[2] + red[3]) * (1.0f / DIM) + 1e-6f);
    const float4 wv = reinterpret_cast<const float4*>(w)[tid];
    const size_t e = (size_t)row * DIM + tid * 4;
    *reinterpret_cast<__half2*>(y + e) =
        __floats2half2_rn(v.x * r * wv.x, v.y * r * wv.y);
    *reinterpret_cast<__half2*>(y + e + 2) =
        __floats2half2_rn(v.z * r * wv.z, v.w * r * wv.w);
}

// ======================= mma.sync GEMM (plain f16, f32 acc) ==============
// 128x128 block tile, 4 warps (64x64 each -> 128 B LDS per mma), 128 threads,
// K-slab 64, 3-stage cp.async, single sync/slab, 2 CTAs/SM.
// EPI: 1 +bias+resid fp32 C; 2 +bias, gelu -> f16 Ch; 3 plain -> f16 Ch
#define PADK   72
#define MATB   (128 * 144)
#define STAGEB (2 * MATB)
#define NSTAGE 3
#define GEMM_DSMEM (NSTAGE * STAGEB)

template <int EPI>
__global__ __launch_bounds__(128, 2)
void gemm_mma(const __half* __restrict__ A, const __half* __restrict__ Bw,
              const float* __restrict__ bias, const float* __restrict__ R,
              float* __restrict__ C, __half* __restrict__ Ch,
              int M, int N, int K) {
    extern __shared__ char dsm[];
    const uint32_t sm0 = smem_u32(dsm);
    const int tid = threadIdx.x;
    const int wid = tid >> 5;
    const int lane = tid & 31;
    const int wm = wid & 1;      // 2 warps over M
    const int wn = wid >> 1;     // 2 warps over N
    const int bm = blockIdx.y * 128;
    const int bn = blockIdx.x * 128;

    const int NS = K / 64;

    auto load_slab = [&](int s, int buf) {
        const uint32_t st = sm0 + (uint32_t)buf * STAGEB;
        const int k0 = s * 64;
        #pragma unroll
        for (int i = 0; i < 8; ++i) {
            const int idx = tid + i * 128;        // 0..1023
            const int row = idx >> 3;             // 0..127
            const int c   = idx & 7;              // 0..7
            const uint32_t so = (uint32_t)(row * 144 + c * 16);
            cp16(st + 0 * MATB + so, A  + (size_t)(bm + row) * K + k0 + c * 8);
            cp16(st + 1 * MATB + so, Bw + (size_t)(bn + row) * K + k0 + c * 8);
        }
    };

    float acc[4][8][4] = {};

    load_slab(0, 0); CP_COMMIT();
    if (NS > 1) load_slab(1, 1);
    CP_COMMIT();

    const uint32_t aRow = (uint32_t)(wm * 64 + (lane & 15));
    const uint32_t aKo  = (uint32_t)((lane >> 4) * 8);
    const uint32_t bRow = (uint32_t)(wn * 64 + (lane & 7) + ((lane >> 4) << 3));
    const uint32_t bKo  = (uint32_t)(((lane >> 3) & 1) * 8);

    int cbuf = 0, lbuf = 2;
    for (int s = 0; s < NS; ++s) {
        CP_WAIT1();
        __syncthreads();
        if (s + 2 < NS) load_slab(s + 2, lbuf);
        CP_COMMIT();
        const uint32_t st = sm0 + (uint32_t)cbuf * STAGEB;
        if (++lbuf == NSTAGE) lbuf = 0;
        if (++cbuf == NSTAGE) cbuf = 0;

        #pragma unroll
        for (int kk = 0; kk < 64; kk += 16) {
            uint32_t bf[4][4];
            #pragma unroll
            for (int g = 0; g < 4; ++g) {
                const uint32_t off = ((bRow + g * 16) * PADK + kk + bKo) * 2;
                ldsm4(bf[g], st + 1 * MATB + off);
            }
            #pragma unroll
            for (int mi = 0; mi < 4; ++mi) {
                uint32_t ah[4];
                const uint32_t off = ((aRow + mi * 16) * PADK + kk + aKo) * 2;
                ldsm4(ah, st + 0 * MATB + off);
                #pragma unroll
                for (int ni = 0; ni < 8; ++ni) {
                    const int g = ni >> 1, sub = (ni & 1) * 2;
                    mma_f32(acc[mi][ni], ah, &bf[g][sub]);
                }
            }
        }
    }

    // epilogue
    const int cbase = bn + wn * 64 + (lane & 3) * 2;
    const int rbase = bm + wm * 64 + (lane >> 2);
    #pragma unroll
    for (int mi = 0; mi < 4; ++mi) {
        #pragma unroll
        for (int ni = 0; ni < 8; ++ni) {
            const int col = cbase + ni * 8;
            #pragma unroll
            for (int half = 0; half < 2; ++half) {
                const int row = rbase + mi * 16 + half * 8;
                float v0 = acc[mi][ni][half * 2 + 0];
                float v1 = acc[mi][ni][half * 2 + 1];
                if (EPI == 1) {
                    const float2 rv = *(const float2*)(R + (size_t)row * N + col);
                    v0 += bias[col]     + rv.x;
                    v1 += bias[col + 1] + rv.y;
                    *(float2*)(C + (size_t)row * N + col) = {v0, v1};
                } else if (EPI == 2) {
                    const float t0 = v0 + bias[col];
                    const float t1 = v1 + bias[col + 1];
                    const float g0 = 0.5f * t0 * (1.0f + erff(t0 * 0.70710678118654752f));
                    const float g1 = 0.5f * t1 * (1.0f + erff(t1 * 0.70710678118654752f));
                    *reinterpret_cast<__half2*>(Ch + (size_t)row * N + col) =
                        __floats2half2_rn(g0, g1);
                } else {
                    *reinterpret_cast<__half2*>(Ch + (size_t)row * N + col) =
                        __floats2half2_rn(v0, v1);
                }
            }
        }
    }
}

// ======================= flash-style banded attention (tensor-core) ==============
// Unchanged from round 14 (passed: 44.6us).
#define AQ_OFF  0
#define AK_OFF  18432
#define AV_OFF  (18432 + 36864)
#define VT_PAD  264
#define ATT_DSMEM (AV_OFF + 64 * VT_PAD * 2)

__global__ __launch_bounds__(256)
void attn_kernel(const __half* __restrict__ qkv,
                 __half* __restrict__ ctx,
                 const int* __restrict__ csp, int T) {
    extern __shared__ char dsm[];
    __half* Qs = (__half*)(dsm + AQ_OFF);
    __half* Ks = (__half*)(dsm + AK_OFF);
    __half* Vt = (__half*)(dsm + AV_OFF);

    const int cs = min(*csp, 64);
    const int tid = threadIdx.x;
    const int wid = tid >> 5;
    const int lane = tid & 31;
    const int q0 = blockIdx.x * 128;
    const int h = blockIdx.y;
    const int b = blockIdx.z;

    const int jlo = max(q0 - cs, 0);
    const int jhi = min(q0 + 127 + cs, T - 1);
    const int nk = jhi - jlo + 1;

    const size_t gbase = (size_t)(b * T) * (3 * DIM) + h * HDIM;

    const __half2 qsc = __float2half2_rn(0.125f);
    for (int i = tid; i < 128 * 8; i += 256) {
        const int row = i >> 3, c = i & 7;
        const __half2* src = (const __half2*)(qkv + gbase + (size_t)(q0 + row) * (3 * DIM) + c * 8);
        __half2* dst = (__half2*)(Qs + row * 72 + c * 8);
        #pragma unroll
        for (int u = 0; u < 4; ++u) dst[u] = __hmul2(src[u], qsc);
    }
    for (int i = tid; i < 256 * 8; i += 256) {
        const int row = i >> 3, c = i & 7;
        uint4 val = {0u, 0u, 0u, 0u};
        if (row < nk)
            val = *(const uint4*)(qkv + gbase + (size_t)(jlo + row) * (3 * DIM) + DIM + c * 8);
        *(uint4*)(Ks + row * 72 + c * 8) = val;
    }
    for (int i = tid; i < 8192; i += 256) {
        const int key = i & 255, dp = i >> 8;
        __half2 v = __floats2half2_rn(0.0f, 0.0f);
        if (key < nk)
            v = *(const __half2*)(qkv + gbase + (size_t)(jlo + key) * (3 * DIM) + 2 * DIM + dp * 2);
        Vt[(2 * dp)     * VT_PAD + key] = __low2half(v);
        Vt[(2 * dp + 1) * VT_PAD + key] = __high2half(v);
    }
    __syncthreads();

    const uint32_t sQ = smem_u32(Qs), sK = smem_u32(Ks), sV = smem_u32(Vt);

    int nb = q0 + wid * 16 - cs - jlo;
    nb = (nb < 0 ? 0 : nb) & ~7;

    const uint32_t aRow = (uint32_t)(wid * 16 + (lane & 15));
    const uint32_t aKo  = (uint32_t)((lane >> 4) * 8);
    uint32_t aq[4][4];
    #pragma unroll
    for (int kk = 0; kk < 4; ++kk)
        ldsm4(aq[kk], sQ + (aRow * 72 + kk * 16 + aKo) * 2);

    const uint32_t bR  = (uint32_t)((lane & 7) + ((lane >> 4) << 3));
    const uint32_t bKo = (uint32_t)(((lane >> 3) & 1) * 8);

    float sacc[18][4] = {};
    #pragma unroll
    for (int ng = 0; ng < 9; ++ng) {
        #pragma unroll
        for (int kk = 0; kk < 4; ++kk) {
            uint32_t bf[4];
            ldsm4(bf, sK + ((uint32_t)(nb + ng * 16 + bR) * 72 + kk * 16 + bKo) * 2);
            mma_f32(sacc[ng * 2],     aq[kk], &bf[0]);
            mma_f32(sacc[ng * 2 + 1], aq[kk], &bf[2]);
        }
    }

    const int r0 = q0 + wid * 16 + (lane >> 2);
    const int r1 = r0 + 8;
    const int cb = jlo + nb + 2 * (lane & 3);
    float m0 = -INFINITY, m1 = -INFINITY;
    #pragma unroll
    for (int t = 0; t < 18; ++t) {
        const int k0 = cb + t * 8, k1 = k0 + 1;
        if (k0 < r0 - cs || k0 > r0 + cs || k0 > jhi) sacc[t][0] = -INFINITY;
        if (k1 < r0 - cs || k1 > r0 + cs || k1 > jhi) sacc[t][1] = -INFINITY;
        if (k0 < r1 - cs || k0 > r1 + cs || k0 > jhi) sacc[t][2] = -INFINITY;
        if (k1 < r1 - cs || k1 > r1 + cs || k1 > jhi) sacc[t][3] = -INFINITY;
        m0 = fmaxf(m0, fmaxf(sacc[t][0], sacc[t][1]));
        m1 = fmaxf(m1, fmaxf(sacc[t][2], sacc[t][3]));
    }
    m0 = fmaxf(m0, __shfl_xor_sync(0xFFFFFFFFu, m0, 1));
    m0 = fmaxf(m0, __shfl_xor_sync(0xFFFFFFFFu, m0, 2));
    m1 = fmaxf(m1, __shfl_xor_sync(0xFFFFFFFFu, m1, 1));
    m1 = fmaxf(m1, __shfl_xor_sync(0xFFFFFFFFu, m1, 2));

    float sum0 = 0.0f, sum1 = 0.0f;
    uint32_t pf[18][2];
    #pragma unroll
    for (int t = 0; t < 18; ++t) {
        const float p00 = __expf(sacc[t][0] - m0);
        const float p01 = __expf(sacc[t][1] - m0);
        const float p10 = __expf(sacc[t][2] - m1);
        const float p11 = __expf(sacc[t][3] - m1);
        sum0 += p00 + p01;
        sum1 += p10 + p11;
        const __half2 h0 = __floats2half2_rn(p00, p01);
        const __half2 h1 = __floats2half2_rn(p10, p11);
        pf[t][0] = *reinterpret_cast<const uint32_t*>(&h0);
        pf[t][1] = *reinterpret_cast<const uint32_t*>(&h1);
    }
    sum0 += __shfl_xor_sync(0xFFFFFFFFu, sum0, 1);
    sum0 += __shfl_xor_sync(0xFFFFFFFFu, sum0, 2);
    sum1 += __shfl_xor_sync(0xFFFFFFFFu, sum1, 1);
    sum1 += __shfl_xor_sync(0xFFFFFFFFu, sum1, 2);
    const float inv0 = 1.0f / sum0;
    const float inv1 = 1.0f / sum1;

    float oacc[8][4] = {};
    #pragma unroll
    for (int j = 0; j < 9; ++j) {
        uint32_t pa[4] = {pf[2 * j][0], pf[2 * j][1], pf[2 * j + 1][0], pf[2 * j + 1][1]};
        #pragma unroll
        for (int ng = 0; ng < 4; ++ng) {
            uint32_t bf[4];
            ldsm4(bf, sV + ((uint32_t)(ng * 16 + bR) * VT_PAD + nb + j * 16 + bKo) * 2);
            mma_f32(oacc[ng * 2],     pa, &bf[0]);
            mma_f32(oacc[ng * 2 + 1], pa, &bf[2]);
        }
    }

    const size_t e0 = (size_t)(b * T + r0) * DIM + h * HDIM;
    const size_t e1 = (size_t)(b * T + r1) * DIM + h * HDIM;
    #pragma unroll
    for (int ni = 0; ni < 8; ++ni) {
        const int d = ni * 8 + 2 * (lane & 3);
        *reinterpret_cast<__half2*>(ctx + e0 + d) =
            __floats2half2_rn(oacc[ni][0] * inv0, oacc[ni][1] * inv0);
        *reinterpret_cast<__half2*>(ctx + e1 + d) =
            __floats2half2_rn(oacc[ni][2] * inv1, oacc[ni][3] * inv1);
    }
}

// ======================= launcher =======================
extern "C" void kernel_launch(void* const* d_in, const int* in_sizes, int n_in,
                              void* d_out, int out_size) {
    const float* x       = (const float*)d_in[0];
    const float* norm1_w = (const float*)d_in[1];
    const float* norm2_w = (const float*)d_in[2];
    const float* w_qkv   = (const float*)d_in[3];
    const float* w_out   = (const float*)d_in[4];
    const float* b_out   = (const float*)d_in[5];
    const float* w1      = (const float*)d_in[6];
    const float* b1      = (const float*)d_in[7];
    const float* w2      = (const float*)d_in[8];
    const float* b2      = (const float*)d_in[9];
    const int*   cs      = (const int*)d_in[10];
    float*       out     = (float*)d_out;

    const int BT = in_sizes[0] / DIM;   // 8192
    const int T  = T_SEQ;
    const int B  = BT / T;

    __half *wqkvT, *woutT, *w1T, *w2T, *xn, *ctx, *hh, *qkvh;
    float *x1;
    cudaGetSymbolAddress((void**)&wqkvT, g_wqkvT);
    cudaGetSymbolAddress((void**)&woutT, g_woutT);
    cudaGetSymbolAddress((void**)&w1T,   g_w1T);
    cudaGetSymbolAddress((void**)&w2T,   g_w2T);
    cudaGetSymbolAddress((void**)&xn,    g_xn);
    cudaGetSymbolAddress((void**)&ctx,   g_ctx);
    cudaGetSymbolAddress((void**)&hh,    g_hh);
    cudaGetSymbolAddress((void**)&qkvh,  g_qkvh);
    cudaGetSymbolAddress((void**)&x1,    g_x1);

    cudaFuncSetAttribute(gemm_mma<1>, cudaFuncAttributeMaxDynamicSharedMemorySize, GEMM_DSMEM);
    cudaFuncSetAttribute(gemm_mma<2>, cudaFuncAttributeMaxDynamicSharedMemorySize, GEMM_DSMEM);
    cudaFuncSetAttribute(gemm_mma<3>, cudaFuncAttributeMaxDynamicSharedMemorySize, GEMM_DSMEM);
    cudaFuncSetAttribute(attn_kernel, cudaFuncAttributeMaxDynamicSharedMemorySize, ATT_DSMEM);

    // 0. all weight preps in one launch
    wprep_all<<<3072, dim3(32, 8)>>>(w_qkv, wqkvT, w_out, woutT, w1, w1T, w2, w2T);

    // 1. xn = rmsnorm(x, norm1_w) -> f16
    rmsnorm_h_kernel<<<BT, 128>>>(x, norm1_w, xn);
    // 2. qkv = xn @ w_qkv -> f16
    gemm_mma<3><<<dim3((3 * DIM) / 128, BT / 128), 128, GEMM_DSMEM>>>(
        xn, wqkvT, nullptr, nullptr, nullptr, qkvh, BT, 3 * DIM, DIM);
    // 3. banded attention (tensor-core) -> ctx f16
    attn_kernel<<<dim3(T / 128, NHEAD, B), 256, ATT_DSMEM>>>(qkvh, ctx, cs, T);
    // 4. x1 = x + ctx @ w_out + b_out (fp32)
    gemm_mma<1><<<dim3(DIM / 128, BT / 128), 128, GEMM_DSMEM>>>(
        ctx, woutT, b_out, x, x1, nullptr, BT, DIM, DIM);
    // 5. xn = rmsnorm(x1, norm2_w) -> f16
    rmsnorm_h_kernel<<<BT, 128>>>(x1, norm2_w, xn);
    // 6. h = gelu(xn @ w1 + b1) -> f16
    gemm_mma<2><<<dim3(FFN_DIM / 128, BT / 128), 128, GEMM_DSMEM>>>(
        xn, w1T, b1, nullptr, nullptr, hh, BT, FFN_DIM, DIM);
    // 7. out = x1 + h @ w2 + b2
    gemm_mma<1><<<dim3(DIM / 128, BT / 128), 128, GEMM_DSMEM>>>(
        hh, w2T, b2, x1, out, nullptr, BT, DIM, FFN_DIM);
}